// round 6
// baseline (speedup 1.0000x reference)
#include <cuda_runtime.h>
#include <math.h>

#define M_ROWS 36928   // B*T = 64*577
#define E_DIM  768
#define H_DIM  64
#define T_LEN  577
#define B_SZ   64
#define GW     24

typedef unsigned long long u64;

// scratch (static device arrays; no allocation)
__device__ float g_q[M_ROWS * H_DIM];
__device__ float g_k[M_ROWS * H_DIM];
__device__ float g_v[M_ROWS * H_DIM];

// ---- packed f32x2 helpers (Blackwell baseline PTX; FFMA2 in SASS) ----------
__device__ __forceinline__ u64 pk2(float lo, float hi) {
    u64 r; asm("mov.b64 %0, {%1, %2};" : "=l"(r) : "f"(lo), "f"(hi)); return r;
}
__device__ __forceinline__ u64 dup2(float v) {
    u64 r; asm("mov.b64 %0, {%1, %1};" : "=l"(r) : "f"(v)); return r;
}
__device__ __forceinline__ void upk2(float& lo, float& hi, u64 v) {
    asm("mov.b64 {%0, %1}, %2;" : "=f"(lo), "=f"(hi) : "l"(v));
}
__device__ __forceinline__ u64 fma2(u64 a, u64 b, u64 c) {
    u64 d; asm("fma.rn.f32x2 %0, %1, %2, %3;" : "=l"(d) : "l"(a), "l"(b), "l"(c)); return d;
}
__device__ __forceinline__ u64 mul2(u64 a, u64 b) {
    u64 d; asm("mul.rn.f32x2 %0, %1, %2;" : "=l"(d) : "l"(a), "l"(b)); return d;
}

// ---------------------------------------------------------------------------
// Kernel 1: fused QKV projection + LayerNorm epilogue, f32x2 inner loop
// grid (289, 3). BM=128, BN=64, BK=16, 256 threads, 8x4 tile (packed as 8x2 u64)
// ---------------------------------------------------------------------------
__global__ __launch_bounds__(256) void qkv_ln_kernel(
    const float* __restrict__ x,
    const float* __restrict__ w_q, const float* __restrict__ w_k, const float* __restrict__ w_v,
    const float* __restrict__ q_gamma, const float* __restrict__ q_beta,
    const float* __restrict__ k_gamma, const float* __restrict__ k_beta)
{
    const int which = blockIdx.y;
    const float* __restrict__ w = (which == 0) ? w_q : (which == 1) ? w_k : w_v;
    float* __restrict__ outg = (which == 0) ? g_q : (which == 1) ? g_k : g_v;
    const float* __restrict__ gamma = (which == 0) ? q_gamma : k_gamma;
    const float* __restrict__ beta  = (which == 0) ? q_beta  : k_beta;

    __shared__ float smem[128 * 65];
    __shared__ float mu_s[128], rstd_s[128];
    float* x_s = smem;               // [16][132]
    float* w_s = smem + 16 * 132;    // [16][68]

    const int m0  = blockIdx.x * 128;
    const int tid = threadIdx.x;
    const int ty  = tid >> 4;
    const int tx  = tid & 15;

    u64 acc2[8][2];
#pragma unroll
    for (int i = 0; i < 8; i++) { acc2[i][0] = 0ull; acc2[i][1] = 0ull; }

    for (int k0 = 0; k0 < E_DIM; k0 += 16) {
#pragma unroll
        for (int i = tid; i < 128 * 16; i += 256) {
            int r = i >> 4, c = i & 15;
            int m = m0 + r;
            float vx = (m < M_ROWS) ? x[(size_t)m * E_DIM + k0 + c] : 0.f;
            x_s[c * 132 + r] = vx;
        }
#pragma unroll
        for (int i = tid; i < 16 * 64; i += 256) {
            int r = i >> 6, c = i & 63;
            w_s[r * 68 + c] = w[(k0 + r) * H_DIM + c];
        }
        __syncthreads();
#pragma unroll
        for (int j = 0; j < 16; j++) {
            float4 xv0 = *(const float4*)&x_s[j * 132 + ty * 8];
            float4 xv1 = *(const float4*)&x_s[j * 132 + ty * 8 + 4];
            float4 wv  = *(const float4*)&w_s[j * 68 + tx * 4];
            u64 w01 = pk2(wv.x, wv.y);
            u64 w23 = pk2(wv.z, wv.w);
            float xr[8] = {xv0.x, xv0.y, xv0.z, xv0.w, xv1.x, xv1.y, xv1.z, xv1.w};
#pragma unroll
            for (int i = 0; i < 8; i++) {
                u64 xd = dup2(xr[i]);
                acc2[i][0] = fma2(xd, w01, acc2[i][0]);
                acc2[i][1] = fma2(xd, w23, acc2[i][1]);
            }
        }
        __syncthreads();
    }

    float* out_s = smem;   // [128][65]
#pragma unroll
    for (int i = 0; i < 8; i++) {
        float a0, a1, a2, a3;
        upk2(a0, a1, acc2[i][0]);
        upk2(a2, a3, acc2[i][1]);
        out_s[(ty * 8 + i) * 65 + tx * 4 + 0] = a0;
        out_s[(ty * 8 + i) * 65 + tx * 4 + 1] = a1;
        out_s[(ty * 8 + i) * 65 + tx * 4 + 2] = a2;
        out_s[(ty * 8 + i) * 65 + tx * 4 + 3] = a3;
    }
    __syncthreads();

    if (which < 2) {
        if (tid < 128) {
            int r = tid;
            if (m0 + r < M_ROWS) {
                float s = 0.f;
#pragma unroll 8
                for (int c = 0; c < 64; c++) s += out_s[r * 65 + c];
                float mu = s * (1.f / 64.f);
                float v2 = 0.f;
#pragma unroll 8
                for (int c = 0; c < 64; c++) {
                    float d = out_s[r * 65 + c] - mu;
                    v2 += d * d;
                }
                mu_s[r]   = mu;
                rstd_s[r] = rsqrtf(v2 * (1.f / 64.f) + 1e-5f);
            }
        }
        __syncthreads();
    }

#pragma unroll
    for (int i = tid; i < 128 * 64; i += 256) {
        int r = i >> 6, c = i & 63;
        int m = m0 + r;
        if (m < M_ROWS) {
            float val = out_s[r * 65 + c];
            if (which < 2)
                val = (val - mu_s[r]) * rstd_s[r] * gamma[c] + beta[c];
            outg[(size_t)m * H_DIM + c] = val;
        }
    }
}

// ---------------------------------------------------------------------------
// Kernel 2 (v4): flash attention, QT=128 KT=128, f32x2 packed sim & PV
// ---------------------------------------------------------------------------
#define QT 128
#define KT 128
#define QS 68
#define PS 132
#define ATTN_SMEM_FLOATS (QT*QS + KT*QS + KT*QS + QT*PS + 5*QT)
#define ATTN_SMEM_BYTES  (ATTN_SMEM_FLOATS * 4)

__global__ __launch_bounds__(256, 1) void attn_kernel(
    const float* __restrict__ w_sigma, const float* __restrict__ b_sigma,
    const float* __restrict__ w_alpha, const float* __restrict__ b_alpha,
    float* __restrict__ out)
{
    extern __shared__ float smf[];
    float* q_s  = smf;                  // [QT][QS]
    float* k_s  = q_s + QT * QS;        // [KT][QS]
    float* v_s  = k_s + KT * QS;        // [KT][QS]
    float* p_s  = v_s + KT * QS;        // [QT][PS]
    float* al_s = p_s + QT * PS;
    float* ix_s = al_s + QT;
    float* iy_s = ix_s + QT;
    float* gx_s = iy_s + QT;
    float* gy_s = gx_s + QT;

    const int b   = blockIdx.y;
    const int q0  = blockIdx.x * QT;
    const int tid = threadIdx.x;
    const int ty  = tid >> 4, tx = tid & 15;
    const size_t base = (size_t)b * T_LEN * H_DIM;

    // load q tile, folding 0.125 = 1/sqrt(H)
#pragma unroll
    for (int i = 0; i < 8; i++) {
        int f4 = tid + i * 256;
        int r = f4 >> 4, c4 = f4 & 15;
        int qi = q0 + r;
        float4 qv = make_float4(0.f, 0.f, 0.f, 0.f);
        if (qi < T_LEN) qv = *(const float4*)&g_q[base + (size_t)qi * H_DIM + c4 * 4];
        qv.x *= 0.125f; qv.y *= 0.125f; qv.z *= 0.125f; qv.w *= 0.125f;
        *(float4*)&q_s[r * QS + c4 * 4] = qv;
    }
    __syncthreads();

    if (tid < QT) {
        int r = tid;
        int qi = q0 + r;
        if (qi >= 1 && qi < T_LEN) {
            float a = 0.f, s0 = 0.f, s1 = 0.f;
#pragma unroll 8
            for (int c = 0; c < 64; c++) {
                float qv = q_s[r * QS + c] * 8.f;
                a  += qv * w_alpha[c];
                s0 += qv * w_sigma[c * 2 + 0];
                s1 += qv * w_sigma[c * 2 + 1];
            }
            a += b_alpha[0]; s0 += b_sigma[0]; s1 += b_sigma[1];
            float alpha = fmaxf(a, 0.f) + log1pf(expf(-fabsf(a)));
            float sx = 1.f / (1.f + expf(-s0));
            float sy = 1.f / (1.f + expf(-s1));
            al_s[r] = alpha * 0.125f;
            ix_s[r] = 0.5f / (sx * sx);
            iy_s[r] = 0.5f / (sy * sy);
            int gq = qi - 1;
            gx_s[r] = (float)(gq % GW);
            gy_s[r] = (float)(gq / GW);
        } else {
            al_s[r] = 0.f; ix_s[r] = 0.f; iy_s[r] = 0.f;
            gx_s[r] = 0.f; gy_s[r] = 0.f;
        }
    }
    __syncthreads();

    float m_i[8], l_i[8], alr[8], ixr[8], iyr[8], qgx[8], qgy[8];
#pragma unroll
    for (int iq = 0; iq < 8; iq++) {
        int r = ty * 8 + iq;
        m_i[iq] = -1e30f;
        l_i[iq] = 0.f;
        alr[iq] = al_s[r]; ixr[iq] = ix_s[r]; iyr[iq] = iy_s[r];
        qgx[iq] = gx_s[r]; qgy[iq] = gy_s[r];
    }

    u64 oacc2[8][2];
#pragma unroll
    for (int i = 0; i < 8; i++) { oacc2[i][0] = 0ull; oacc2[i][1] = 0ull; }

    for (int k0 = 0; k0 < T_LEN; k0 += KT) {
#pragma unroll
        for (int i = 0; i < 8; i++) {
            int f4 = tid + i * 256;
            int r = f4 >> 4, c4 = f4 & 15;
            int ki = k0 + r;
            float4 kv = make_float4(0.f, 0.f, 0.f, 0.f);
            float4 vv = kv;
            if (ki < T_LEN) {
                kv = *(const float4*)&g_k[base + (size_t)ki * H_DIM + c4 * 4];
                vv = *(const float4*)&g_v[base + (size_t)ki * H_DIM + c4 * 4];
            }
            *(float4*)&k_s[r * QS + c4 * 4] = kv;
            *(float4*)&v_s[r * QS + c4 * 4] = vv;
        }
        __syncthreads();

        // sim: 8q x 8k, packed over ik pairs -> s2[8][4]
        u64 s2[8][4];
#pragma unroll
        for (int i = 0; i < 8; i++)
#pragma unroll
            for (int p = 0; p < 4; p++) s2[i][p] = 0ull;

#pragma unroll 2
        for (int j4 = 0; j4 < 16; j4++) {
            float4 kv[8];
#pragma unroll
            for (int j = 0; j < 8; j++)
                kv[j] = *(const float4*)&k_s[(tx + 16 * j) * QS + j4 * 4];
            u64 kx[4], ky[4], kz[4], kw[4];
#pragma unroll
            for (int p = 0; p < 4; p++) {
                kx[p] = pk2(kv[2 * p].x, kv[2 * p + 1].x);
                ky[p] = pk2(kv[2 * p].y, kv[2 * p + 1].y);
                kz[p] = pk2(kv[2 * p].z, kv[2 * p + 1].z);
                kw[p] = pk2(kv[2 * p].w, kv[2 * p + 1].w);
            }
#pragma unroll
            for (int iq = 0; iq < 8; iq++) {
                float4 qv = *(const float4*)&q_s[(ty * 8 + iq) * QS + j4 * 4];
                u64 qx = dup2(qv.x), qy = dup2(qv.y), qz = dup2(qv.z), qw = dup2(qv.w);
#pragma unroll
                for (int p = 0; p < 4; p++) {
                    s2[iq][p] = fma2(qx, kx[p], s2[iq][p]);
                    s2[iq][p] = fma2(qy, ky[p], s2[iq][p]);
                    s2[iq][p] = fma2(qz, kz[p], s2[iq][p]);
                    s2[iq][p] = fma2(qw, kw[p], s2[iq][p]);
                }
            }
        }

        // unpack to scalars
        float s[8][8];
#pragma unroll
        for (int iq = 0; iq < 8; iq++)
#pragma unroll
            for (int p = 0; p < 4; p++)
                upk2(s[iq][2 * p], s[iq][2 * p + 1], s2[iq][p]);

        // Gaussian augmentation + mask
#pragma unroll
        for (int ik = 0; ik < 8; ik++) {
            int ki = k0 + tx + 16 * ik;
            bool kvalid = (ki < T_LEN);
            bool kaug = (ki >= 1) && kvalid;
            int g = kaug ? ki - 1 : 0;
            float kgx = (float)(g % GW);
            float kgy = (float)(g / GW);
#pragma unroll
            for (int iq = 0; iq < 8; iq++) {
                float val = s[iq][ik];
                if (kaug) {
                    float dgx = qgx[iq] - kgx;
                    float dgy = qgy[iq] - kgy;
                    val += alr[iq] * __expf(-dgx * dgx * ixr[iq] - dgy * dgy * iyr[iq]);
                }
                if (!kvalid) val = -1e30f;
                s[iq][ik] = val;
            }
        }

        // register softmax over 16 tx lanes
        float mloc[8];
#pragma unroll
        for (int iq = 0; iq < 8; iq++) {
            float mm = s[iq][0];
#pragma unroll
            for (int ik = 1; ik < 8; ik++) mm = fmaxf(mm, s[iq][ik]);
            mloc[iq] = mm;
        }
#pragma unroll
        for (int o = 8; o >= 1; o >>= 1)
#pragma unroll
            for (int iq = 0; iq < 8; iq++)
                mloc[iq] = fmaxf(mloc[iq], __shfl_xor_sync(0xffffffffu, mloc[iq], o));

        float rs[8];
#pragma unroll
        for (int iq = 0; iq < 8; iq++) {
            float mnew = fmaxf(m_i[iq], mloc[iq]);
            float scf = __expf(m_i[iq] - mnew);
            m_i[iq] = mnew;
            float sum = 0.f;
#pragma unroll
            for (int ik = 0; ik < 8; ik++) {
                float p = __expf(s[iq][ik] - mnew);
                s[iq][ik] = p;
                sum += p;
            }
            rs[iq] = sum;
            l_i[iq] *= scf;
            u64 sc2 = dup2(scf);
            oacc2[iq][0] = mul2(oacc2[iq][0], sc2);
            oacc2[iq][1] = mul2(oacc2[iq][1], sc2);
        }
#pragma unroll
        for (int o = 8; o >= 1; o >>= 1)
#pragma unroll
            for (int iq = 0; iq < 8; iq++)
                rs[iq] += __shfl_xor_sync(0xffffffffu, rs[iq], o);
#pragma unroll
        for (int iq = 0; iq < 8; iq++) l_i[iq] += rs[iq];

        // stage P to smem (strided k positions)
#pragma unroll
        for (int iq = 0; iq < 8; iq++)
#pragma unroll
            for (int ik = 0; ik < 8; ik++)
                p_s[(ty * 8 + iq) * PS + tx + 16 * ik] = s[iq][ik];
        __syncthreads();

        // P @ V packed over h: oacc2[iq][0]=(h0,h1) oacc2[iq][1]=(h2,h3)
#pragma unroll 2
        for (int kc4 = 0; kc4 < KT / 4; kc4++) {
            float4 pr[8];
#pragma unroll
            for (int iq = 0; iq < 8; iq++)
                pr[iq] = *(const float4*)&p_s[(ty * 8 + iq) * PS + kc4 * 4];
            u64 v01[4], v23[4];
#pragma unroll
            for (int j = 0; j < 4; j++) {
                float4 vv = *(const float4*)&v_s[(kc4 * 4 + j) * QS + tx * 4];
                v01[j] = pk2(vv.x, vv.y);
                v23[j] = pk2(vv.z, vv.w);
            }
#pragma unroll
            for (int iq = 0; iq < 8; iq++) {
                u64 p0 = dup2(pr[iq].x), p1 = dup2(pr[iq].y);
                u64 p2 = dup2(pr[iq].z), p3 = dup2(pr[iq].w);
                oacc2[iq][0] = fma2(p0, v01[0], oacc2[iq][0]);
                oacc2[iq][1] = fma2(p0, v23[0], oacc2[iq][1]);
                oacc2[iq][0] = fma2(p1, v01[1], oacc2[iq][0]);
                oacc2[iq][1] = fma2(p1, v23[1], oacc2[iq][1]);
                oacc2[iq][0] = fma2(p2, v01[2], oacc2[iq][0]);
                oacc2[iq][1] = fma2(p2, v23[2], oacc2[iq][1]);
                oacc2[iq][0] = fma2(p3, v01[3], oacc2[iq][0]);
                oacc2[iq][1] = fma2(p3, v23[3], oacc2[iq][1]);
            }
        }
        __syncthreads();
    }

    // final normalize + write
#pragma unroll
    for (int iq = 0; iq < 8; iq++) {
        int r = ty * 8 + iq;
        int qi = q0 + r;
        if (qi < T_LEN) {
            float inv = 1.f / l_i[iq];
            float o0, o1, o2, o3;
            upk2(o0, o1, oacc2[iq][0]);
            upk2(o2, o3, oacc2[iq][1]);
            float4 o = make_float4(o0 * inv, o1 * inv, o2 * inv, o3 * inv);
            *(float4*)&out[base + (size_t)qi * H_DIM + tx * 4] = o;
        }
    }
}

// ---------------------------------------------------------------------------
extern "C" void kernel_launch(void* const* d_in, const int* in_sizes, int n_in,
                              void* d_out, int out_size)
{
    const float* x       = (const float*)d_in[0];
    const float* w_q     = (const float*)d_in[1];
    const float* w_k     = (const float*)d_in[2];
    const float* w_v     = (const float*)d_in[3];
    const float* q_gamma = (const float*)d_in[4];
    const float* q_beta  = (const float*)d_in[5];
    const float* k_gamma = (const float*)d_in[6];
    const float* k_beta  = (const float*)d_in[7];
    const float* w_sigma = (const float*)d_in[8];
    const float* b_sigma = (const float*)d_in[9];
    const float* w_alpha = (const float*)d_in[10];
    const float* b_alpha = (const float*)d_in[11];
    float* out = (float*)d_out;

    dim3 grid1((M_ROWS + 127) / 128, 3);
    qkv_ln_kernel<<<grid1, 256>>>(x, w_q, w_k, w_v, q_gamma, q_beta, k_gamma, k_beta);

    cudaFuncSetAttribute(attn_kernel, cudaFuncAttributeMaxDynamicSharedMemorySize,
                         ATTN_SMEM_BYTES);
    dim3 grid2((T_LEN + QT - 1) / QT, B_SZ);
    attn_kernel<<<grid2, 256, ATTN_SMEM_BYTES>>>(w_sigma, b_sigma, w_alpha, b_alpha, out);
}

// round 7
// speedup vs baseline: 1.0306x; 1.0306x over previous
#include <cuda_runtime.h>
#include <math.h>

#define M_ROWS 36928   // B*T = 64*577
#define E_DIM  768
#define H_DIM  64
#define T_LEN  577
#define B_SZ   64
#define GW     24

typedef unsigned long long u64;

// scratch (static device arrays; no allocation)
__device__ float g_q[M_ROWS * H_DIM];
__device__ float g_k[M_ROWS * H_DIM];
__device__ float g_v[M_ROWS * H_DIM];

// ---- packed f32x2 helpers (issue-slot compression; used in qkv only) -------
__device__ __forceinline__ u64 pk2(float lo, float hi) {
    u64 r; asm("mov.b64 %0, {%1, %2};" : "=l"(r) : "f"(lo), "f"(hi)); return r;
}
__device__ __forceinline__ u64 dup2(float v) {
    u64 r; asm("mov.b64 %0, {%1, %1};" : "=l"(r) : "f"(v)); return r;
}
__device__ __forceinline__ void upk2(float& lo, float& hi, u64 v) {
    asm("mov.b64 {%0, %1}, %2;" : "=f"(lo), "=f"(hi) : "l"(v));
}
__device__ __forceinline__ u64 fma2(u64 a, u64 b, u64 c) {
    u64 d; asm("fma.rn.f32x2 %0, %1, %2, %3;" : "=l"(d) : "l"(a), "l"(b), "l"(c)); return d;
}

// ---------------------------------------------------------------------------
// Kernel 1: fused QKV projection + LayerNorm epilogue (R6 f32x2 version)
// ---------------------------------------------------------------------------
__global__ __launch_bounds__(256) void qkv_ln_kernel(
    const float* __restrict__ x,
    const float* __restrict__ w_q, const float* __restrict__ w_k, const float* __restrict__ w_v,
    const float* __restrict__ q_gamma, const float* __restrict__ q_beta,
    const float* __restrict__ k_gamma, const float* __restrict__ k_beta)
{
    const int which = blockIdx.y;
    const float* __restrict__ w = (which == 0) ? w_q : (which == 1) ? w_k : w_v;
    float* __restrict__ outg = (which == 0) ? g_q : (which == 1) ? g_k : g_v;
    const float* __restrict__ gamma = (which == 0) ? q_gamma : k_gamma;
    const float* __restrict__ beta  = (which == 0) ? q_beta  : k_beta;

    __shared__ float smem[128 * 65];
    __shared__ float mu_s[128], rstd_s[128];
    float* x_s = smem;               // [16][132]
    float* w_s = smem + 16 * 132;    // [16][68]

    const int m0  = blockIdx.x * 128;
    const int tid = threadIdx.x;
    const int ty  = tid >> 4;
    const int tx  = tid & 15;

    u64 acc2[8][2];
#pragma unroll
    for (int i = 0; i < 8; i++) { acc2[i][0] = 0ull; acc2[i][1] = 0ull; }

    for (int k0 = 0; k0 < E_DIM; k0 += 16) {
#pragma unroll
        for (int i = tid; i < 128 * 16; i += 256) {
            int r = i >> 4, c = i & 15;
            int m = m0 + r;
            float vx = (m < M_ROWS) ? x[(size_t)m * E_DIM + k0 + c] : 0.f;
            x_s[c * 132 + r] = vx;
        }
#pragma unroll
        for (int i = tid; i < 16 * 64; i += 256) {
            int r = i >> 6, c = i & 63;
            w_s[r * 68 + c] = w[(k0 + r) * H_DIM + c];
        }
        __syncthreads();
#pragma unroll
        for (int j = 0; j < 16; j++) {
            float4 xv0 = *(const float4*)&x_s[j * 132 + ty * 8];
            float4 xv1 = *(const float4*)&x_s[j * 132 + ty * 8 + 4];
            float4 wv  = *(const float4*)&w_s[j * 68 + tx * 4];
            u64 w01 = pk2(wv.x, wv.y);
            u64 w23 = pk2(wv.z, wv.w);
            float xr[8] = {xv0.x, xv0.y, xv0.z, xv0.w, xv1.x, xv1.y, xv1.z, xv1.w};
#pragma unroll
            for (int i = 0; i < 8; i++) {
                u64 xd = dup2(xr[i]);
                acc2[i][0] = fma2(xd, w01, acc2[i][0]);
                acc2[i][1] = fma2(xd, w23, acc2[i][1]);
            }
        }
        __syncthreads();
    }

    float* out_s = smem;   // [128][65]
#pragma unroll
    for (int i = 0; i < 8; i++) {
        float a0, a1, a2, a3;
        upk2(a0, a1, acc2[i][0]);
        upk2(a2, a3, acc2[i][1]);
        out_s[(ty * 8 + i) * 65 + tx * 4 + 0] = a0;
        out_s[(ty * 8 + i) * 65 + tx * 4 + 1] = a1;
        out_s[(ty * 8 + i) * 65 + tx * 4 + 2] = a2;
        out_s[(ty * 8 + i) * 65 + tx * 4 + 3] = a3;
    }
    __syncthreads();

    if (which < 2) {
        if (tid < 128) {
            int r = tid;
            if (m0 + r < M_ROWS) {
                float s = 0.f;
#pragma unroll 8
                for (int c = 0; c < 64; c++) s += out_s[r * 65 + c];
                float mu = s * (1.f / 64.f);
                float v2 = 0.f;
#pragma unroll 8
                for (int c = 0; c < 64; c++) {
                    float d = out_s[r * 65 + c] - mu;
                    v2 += d * d;
                }
                mu_s[r]   = mu;
                rstd_s[r] = rsqrtf(v2 * (1.f / 64.f) + 1e-5f);
            }
        }
        __syncthreads();
    }

#pragma unroll
    for (int i = tid; i < 128 * 64; i += 256) {
        int r = i >> 6, c = i & 63;
        int m = m0 + r;
        if (m < M_ROWS) {
            float val = out_s[r * 65 + c];
            if (which < 2)
                val = (val - mu_s[r]) * rstd_s[r] * gamma[c] + beta[c];
            outg[(size_t)m * H_DIM + c] = val;
        }
    }
}

// ---------------------------------------------------------------------------
// Kernel 2 (v5): flash attention, QT=128 KT=64, 256 threads, 2 CTAs/SM
// ty = tid>>4 (16 groups x 8 q rows), tx = tid&15
// sim: 8q x 4k per thread (k = tx + 16*ik), PV: 8q x 4h (h = tx*4..+3)
// aug params live in smem (reg budget 128 for occupancy 2)
// ---------------------------------------------------------------------------
#define QT 128
#define KT 64
#define QS 68
#define ATTN_SMEM_FLOATS (QT*QS + KT*QS + KT*QS + QT*QS + 5*QT)
#define ATTN_SMEM_BYTES  (ATTN_SMEM_FLOATS * 4)

__global__ __launch_bounds__(256, 2) void attn_kernel(
    const float* __restrict__ w_sigma, const float* __restrict__ b_sigma,
    const float* __restrict__ w_alpha, const float* __restrict__ b_alpha,
    float* __restrict__ out)
{
    extern __shared__ float smf[];
    float* q_s  = smf;                  // [QT][QS]
    float* k_s  = q_s + QT * QS;        // [KT][QS]
    float* v_s  = k_s + KT * QS;        // [KT][QS]
    float* p_s  = v_s + KT * QS;        // [QT][QS]
    float* al_s = p_s + QT * QS;        // [QT] x5
    float* ix_s = al_s + QT;
    float* iy_s = ix_s + QT;
    float* gx_s = iy_s + QT;
    float* gy_s = gx_s + QT;

    const int b   = blockIdx.y;
    const int q0  = blockIdx.x * QT;
    const int tid = threadIdx.x;
    const int ty  = tid >> 4, tx = tid & 15;
    const size_t base = (size_t)b * T_LEN * H_DIM;

    // load q tile, folding 0.125 = 1/sqrt(H)
#pragma unroll
    for (int i = 0; i < 8; i++) {
        int f4 = tid + i * 256;
        int r = f4 >> 4, c4 = f4 & 15;
        int qi = q0 + r;
        float4 qv = make_float4(0.f, 0.f, 0.f, 0.f);
        if (qi < T_LEN) qv = *(const float4*)&g_q[base + (size_t)qi * H_DIM + c4 * 4];
        qv.x *= 0.125f; qv.y *= 0.125f; qv.z *= 0.125f; qv.w *= 0.125f;
        *(float4*)&q_s[r * QS + c4 * 4] = qv;
    }
    __syncthreads();

    // per-q-row augmentation params (alpha pre-scaled by 0.125)
    if (tid < QT) {
        int r = tid;
        int qi = q0 + r;
        if (qi >= 1 && qi < T_LEN) {
            float a = 0.f, s0 = 0.f, s1 = 0.f;
#pragma unroll 8
            for (int c = 0; c < 64; c++) {
                float qv = q_s[r * QS + c] * 8.f;
                a  += qv * w_alpha[c];
                s0 += qv * w_sigma[c * 2 + 0];
                s1 += qv * w_sigma[c * 2 + 1];
            }
            a += b_alpha[0]; s0 += b_sigma[0]; s1 += b_sigma[1];
            float alpha = fmaxf(a, 0.f) + log1pf(expf(-fabsf(a)));
            float sx = 1.f / (1.f + expf(-s0));
            float sy = 1.f / (1.f + expf(-s1));
            al_s[r] = alpha * 0.125f;
            ix_s[r] = 0.5f / (sx * sx);
            iy_s[r] = 0.5f / (sy * sy);
            int gq = qi - 1;
            gx_s[r] = (float)(gq % GW);
            gy_s[r] = (float)(gq / GW);
        } else {
            al_s[r] = 0.f; ix_s[r] = 0.f; iy_s[r] = 0.f;
            gx_s[r] = 0.f; gy_s[r] = 0.f;
        }
    }
    __syncthreads();

    float m_i[8], l_i[8];
#pragma unroll
    for (int iq = 0; iq < 8; iq++) { m_i[iq] = -1e30f; l_i[iq] = 0.f; }

    float oacc[8][4];
#pragma unroll
    for (int i = 0; i < 8; i++)
#pragma unroll
        for (int j = 0; j < 4; j++) oacc[i][j] = 0.f;

    for (int k0 = 0; k0 < T_LEN; k0 += KT) {
        // load K/V tile (64 rows x 64 cols, float4, coalesced)
#pragma unroll
        for (int i = 0; i < 4; i++) {
            int f4 = tid + i * 256;                 // 0..1023
            int r = f4 >> 4, c4 = f4 & 15;
            int ki = k0 + r;
            float4 kv = make_float4(0.f, 0.f, 0.f, 0.f);
            float4 vv = kv;
            if (ki < T_LEN) {
                kv = *(const float4*)&g_k[base + (size_t)ki * H_DIM + c4 * 4];
                vv = *(const float4*)&g_v[base + (size_t)ki * H_DIM + c4 * 4];
            }
            *(float4*)&k_s[r * QS + c4 * 4] = kv;
            *(float4*)&v_s[r * QS + c4 * 4] = vv;
        }
        __syncthreads();

        // sim: 8q x 4k per thread (k strided tx + 16*ik)
        float s[8][4];
#pragma unroll
        for (int i = 0; i < 8; i++)
#pragma unroll
            for (int j = 0; j < 4; j++) s[i][j] = 0.f;

#pragma unroll 2
        for (int j4 = 0; j4 < 16; j4++) {
            float4 kv[4];
#pragma unroll
            for (int j = 0; j < 4; j++)
                kv[j] = *(const float4*)&k_s[(tx + 16 * j) * QS + j4 * 4];
#pragma unroll
            for (int iq = 0; iq < 8; iq++) {
                float4 qv = *(const float4*)&q_s[(ty * 8 + iq) * QS + j4 * 4];
#pragma unroll
                for (int ik = 0; ik < 4; ik++)
                    s[iq][ik] += qv.x * kv[ik].x + qv.y * kv[ik].y +
                                 qv.z * kv[ik].z + qv.w * kv[ik].w;
            }
        }

        // Gaussian augmentation + mask (params from smem per iq)
#pragma unroll
        for (int iq = 0; iq < 8; iq++) {
            int r = ty * 8 + iq;
            float alr = al_s[r], ixr = ix_s[r], iyr = iy_s[r];
            float qgx = gx_s[r], qgy = gy_s[r];
#pragma unroll
            for (int ik = 0; ik < 4; ik++) {
                int ki = k0 + tx + 16 * ik;
                bool kvalid = (ki < T_LEN);
                bool kaug = (ki >= 1) && kvalid;
                int g = kaug ? ki - 1 : 0;
                float kgx = (float)(g % GW);
                float kgy = (float)(g / GW);
                float val = s[iq][ik];
                if (kaug) {
                    float dgx = qgx - kgx;
                    float dgy = qgy - kgy;
                    val += alr * __expf(-dgx * dgx * ixr - dgy * dgy * iyr);
                }
                if (!kvalid) val = -1e30f;
                s[iq][ik] = val;
            }
        }

        // register softmax over 16 tx lanes
        float mloc[8];
#pragma unroll
        for (int iq = 0; iq < 8; iq++)
            mloc[iq] = fmaxf(fmaxf(s[iq][0], s[iq][1]), fmaxf(s[iq][2], s[iq][3]));
#pragma unroll
        for (int o = 8; o >= 1; o >>= 1)
#pragma unroll
            for (int iq = 0; iq < 8; iq++)
                mloc[iq] = fmaxf(mloc[iq], __shfl_xor_sync(0xffffffffu, mloc[iq], o));

        float rs[8];
#pragma unroll
        for (int iq = 0; iq < 8; iq++) {
            float mnew = fmaxf(m_i[iq], mloc[iq]);
            float scf = __expf(m_i[iq] - mnew);
            m_i[iq] = mnew;
            float sum = 0.f;
#pragma unroll
            for (int ik = 0; ik < 4; ik++) {
                float p = __expf(s[iq][ik] - mnew);
                s[iq][ik] = p;
                sum += p;
            }
            rs[iq] = sum;
            l_i[iq] *= scf;
#pragma unroll
            for (int ih = 0; ih < 4; ih++) oacc[iq][ih] *= scf;
        }
#pragma unroll
        for (int o = 8; o >= 1; o >>= 1)
#pragma unroll
            for (int iq = 0; iq < 8; iq++)
                rs[iq] += __shfl_xor_sync(0xffffffffu, rs[iq], o);
#pragma unroll
        for (int iq = 0; iq < 8; iq++) l_i[iq] += rs[iq];

        // stage P (exp'd) to smem at strided k positions
#pragma unroll
        for (int iq = 0; iq < 8; iq++)
#pragma unroll
            for (int ik = 0; ik < 4; ik++)
                p_s[(ty * 8 + iq) * QS + tx + 16 * ik] = s[iq][ik];
        __syncthreads();

        // P @ V: 8q x 4h per thread, k = 64
#pragma unroll 2
        for (int kc4 = 0; kc4 < KT / 4; kc4++) {
            float4 vv[4];
#pragma unroll
            for (int j = 0; j < 4; j++)
                vv[j] = *(const float4*)&v_s[(kc4 * 4 + j) * QS + tx * 4];
#pragma unroll
            for (int iq = 0; iq < 8; iq++) {
                float4 pr = *(const float4*)&p_s[(ty * 8 + iq) * QS + kc4 * 4];
                oacc[iq][0] += pr.x * vv[0].x + pr.y * vv[1].x +
                               pr.z * vv[2].x + pr.w * vv[3].x;
                oacc[iq][1] += pr.x * vv[0].y + pr.y * vv[1].y +
                               pr.z * vv[2].y + pr.w * vv[3].y;
                oacc[iq][2] += pr.x * vv[0].z + pr.y * vv[1].z +
                               pr.z * vv[2].z + pr.w * vv[3].z;
                oacc[iq][3] += pr.x * vv[0].w + pr.y * vv[1].w +
                               pr.z * vv[2].w + pr.w * vv[3].w;
            }
        }
        __syncthreads();
    }

    // final normalize + write
#pragma unroll
    for (int iq = 0; iq < 8; iq++) {
        int r = ty * 8 + iq;
        int qi = q0 + r;
        if (qi < T_LEN) {
            float inv = 1.f / l_i[iq];
            float4 o;
            o.x = oacc[iq][0] * inv;
            o.y = oacc[iq][1] * inv;
            o.z = oacc[iq][2] * inv;
            o.w = oacc[iq][3] * inv;
            *(float4*)&out[base + (size_t)qi * H_DIM + tx * 4] = o;
        }
    }
}

// ---------------------------------------------------------------------------
extern "C" void kernel_launch(void* const* d_in, const int* in_sizes, int n_in,
                              void* d_out, int out_size)
{
    const float* x       = (const float*)d_in[0];
    const float* w_q     = (const float*)d_in[1];
    const float* w_k     = (const float*)d_in[2];
    const float* w_v     = (const float*)d_in[3];
    const float* q_gamma = (const float*)d_in[4];
    const float* q_beta  = (const float*)d_in[5];
    const float* k_gamma = (const float*)d_in[6];
    const float* k_beta  = (const float*)d_in[7];
    const float* w_sigma = (const float*)d_in[8];
    const float* b_sigma = (const float*)d_in[9];
    const float* w_alpha = (const float*)d_in[10];
    const float* b_alpha = (const float*)d_in[11];
    float* out = (float*)d_out;

    dim3 grid1((M_ROWS + 127) / 128, 3);
    qkv_ln_kernel<<<grid1, 256>>>(x, w_q, w_k, w_v, q_gamma, q_beta, k_gamma, k_beta);

    cudaFuncSetAttribute(attn_kernel, cudaFuncAttributeMaxDynamicSharedMemorySize,
                         ATTN_SMEM_BYTES);
    dim3 grid2((T_LEN + QT - 1) / QT, B_SZ);
    attn_kernel<<<grid2, 256, ATTN_SMEM_BYTES>>>(w_sigma, b_sigma, w_alpha, b_alpha, out);
}

// round 8
// speedup vs baseline: 1.0313x; 1.0006x over previous
#include <cuda_runtime.h>
#include <math.h>

#define M_ROWS 36928   // B*T = 64*577
#define E_DIM  768
#define H_DIM  64
#define T_LEN  577
#define B_SZ   64
#define GW     24

typedef unsigned long long u64;

// scratch (static device arrays; no allocation)
__device__ float g_q[M_ROWS * H_DIM];
__device__ float g_k[M_ROWS * H_DIM];
__device__ float g_v[M_ROWS * H_DIM];

// ---- packed f32x2 helpers (issue-slot compression; used in qkv only) -------
__device__ __forceinline__ u64 pk2(float lo, float hi) {
    u64 r; asm("mov.b64 %0, {%1, %2};" : "=l"(r) : "f"(lo), "f"(hi)); return r;
}
__device__ __forceinline__ u64 dup2(float v) {
    u64 r; asm("mov.b64 %0, {%1, %1};" : "=l"(r) : "f"(v)); return r;
}
__device__ __forceinline__ void upk2(float& lo, float& hi, u64 v) {
    asm("mov.b64 {%0, %1}, %2;" : "=f"(lo), "=f"(hi) : "l"(v));
}
__device__ __forceinline__ u64 fma2(u64 a, u64 b, u64 c) {
    u64 d; asm("fma.rn.f32x2 %0, %1, %2, %3;" : "=l"(d) : "l"(a), "l"(b), "l"(c)); return d;
}

// ---------------------------------------------------------------------------
// Kernel 1: fused QKV projection + LayerNorm epilogue (R6 f32x2 version)
// ---------------------------------------------------------------------------
__global__ __launch_bounds__(256) void qkv_ln_kernel(
    const float* __restrict__ x,
    const float* __restrict__ w_q, const float* __restrict__ w_k, const float* __restrict__ w_v,
    const float* __restrict__ q_gamma, const float* __restrict__ q_beta,
    const float* __restrict__ k_gamma, const float* __restrict__ k_beta)
{
    const int which = blockIdx.y;
    const float* __restrict__ w = (which == 0) ? w_q : (which == 1) ? w_k : w_v;
    float* __restrict__ outg = (which == 0) ? g_q : (which == 1) ? g_k : g_v;
    const float* __restrict__ gamma = (which == 0) ? q_gamma : k_gamma;
    const float* __restrict__ beta  = (which == 0) ? q_beta  : k_beta;

    __shared__ float smem[128 * 65];
    __shared__ float mu_s[128], rstd_s[128];
    float* x_s = smem;               // [16][132]
    float* w_s = smem + 16 * 132;    // [16][68]

    const int m0  = blockIdx.x * 128;
    const int tid = threadIdx.x;
    const int ty  = tid >> 4;
    const int tx  = tid & 15;

    u64 acc2[8][2];
#pragma unroll
    for (int i = 0; i < 8; i++) { acc2[i][0] = 0ull; acc2[i][1] = 0ull; }

    for (int k0 = 0; k0 < E_DIM; k0 += 16) {
#pragma unroll
        for (int i = tid; i < 128 * 16; i += 256) {
            int r = i >> 4, c = i & 15;
            int m = m0 + r;
            float vx = (m < M_ROWS) ? x[(size_t)m * E_DIM + k0 + c] : 0.f;
            x_s[c * 132 + r] = vx;
        }
#pragma unroll
        for (int i = tid; i < 16 * 64; i += 256) {
            int r = i >> 6, c = i & 63;
            w_s[r * 68 + c] = w[(k0 + r) * H_DIM + c];
        }
        __syncthreads();
#pragma unroll
        for (int j = 0; j < 16; j++) {
            float4 xv0 = *(const float4*)&x_s[j * 132 + ty * 8];
            float4 xv1 = *(const float4*)&x_s[j * 132 + ty * 8 + 4];
            float4 wv  = *(const float4*)&w_s[j * 68 + tx * 4];
            u64 w01 = pk2(wv.x, wv.y);
            u64 w23 = pk2(wv.z, wv.w);
            float xr[8] = {xv0.x, xv0.y, xv0.z, xv0.w, xv1.x, xv1.y, xv1.z, xv1.w};
#pragma unroll
            for (int i = 0; i < 8; i++) {
                u64 xd = dup2(xr[i]);
                acc2[i][0] = fma2(xd, w01, acc2[i][0]);
                acc2[i][1] = fma2(xd, w23, acc2[i][1]);
            }
        }
        __syncthreads();
    }

    float* out_s = smem;   // [128][65]
#pragma unroll
    for (int i = 0; i < 8; i++) {
        float a0, a1, a2, a3;
        upk2(a0, a1, acc2[i][0]);
        upk2(a2, a3, acc2[i][1]);
        out_s[(ty * 8 + i) * 65 + tx * 4 + 0] = a0;
        out_s[(ty * 8 + i) * 65 + tx * 4 + 1] = a1;
        out_s[(ty * 8 + i) * 65 + tx * 4 + 2] = a2;
        out_s[(ty * 8 + i) * 65 + tx * 4 + 3] = a3;
    }
    __syncthreads();

    if (which < 2) {
        if (tid < 128) {
            int r = tid;
            if (m0 + r < M_ROWS) {
                float s = 0.f;
#pragma unroll 8
                for (int c = 0; c < 64; c++) s += out_s[r * 65 + c];
                float mu = s * (1.f / 64.f);
                float v2 = 0.f;
#pragma unroll 8
                for (int c = 0; c < 64; c++) {
                    float d = out_s[r * 65 + c] - mu;
                    v2 += d * d;
                }
                mu_s[r]   = mu;
                rstd_s[r] = rsqrtf(v2 * (1.f / 64.f) + 1e-5f);
            }
        }
        __syncthreads();
    }

#pragma unroll
    for (int i = tid; i < 128 * 64; i += 256) {
        int r = i >> 6, c = i & 63;
        int m = m0 + r;
        if (m < M_ROWS) {
            float val = out_s[r * 65 + c];
            if (which < 2)
                val = (val - mu_s[r]) * rstd_s[r] * gamma[c] + beta[c];
            outg[(size_t)m * H_DIM + c] = val;
        }
    }
}

// ---------------------------------------------------------------------------
// Kernel 2 (v5): flash attention, QT=128 KT=64, 256 threads, 2 CTAs/SM
// ty = tid>>4 (16 groups x 8 q rows), tx = tid&15
// sim: 8q x 4k per thread (k = tx + 16*ik), PV: 8q x 4h (h = tx*4..+3)
// aug params live in smem (reg budget 128 for occupancy 2)
// ---------------------------------------------------------------------------
#define QT 128
#define KT 64
#define QS 68
#define ATTN_SMEM_FLOATS (QT*QS + KT*QS + KT*QS + QT*QS + 5*QT)
#define ATTN_SMEM_BYTES  (ATTN_SMEM_FLOATS * 4)

__global__ __launch_bounds__(256, 2) void attn_kernel(
    const float* __restrict__ w_sigma, const float* __restrict__ b_sigma,
    const float* __restrict__ w_alpha, const float* __restrict__ b_alpha,
    float* __restrict__ out)
{
    extern __shared__ float smf[];
    float* q_s  = smf;                  // [QT][QS]
    float* k_s  = q_s + QT * QS;        // [KT][QS]
    float* v_s  = k_s + KT * QS;        // [KT][QS]
    float* p_s  = v_s + KT * QS;        // [QT][QS]
    float* al_s = p_s + QT * QS;        // [QT] x5
    float* ix_s = al_s + QT;
    float* iy_s = ix_s + QT;
    float* gx_s = iy_s + QT;
    float* gy_s = gx_s + QT;

    const int b   = blockIdx.y;
    const int q0  = blockIdx.x * QT;
    const int tid = threadIdx.x;
    const int ty  = tid >> 4, tx = tid & 15;
    const size_t base = (size_t)b * T_LEN * H_DIM;

    // load q tile, folding 0.125 = 1/sqrt(H)
#pragma unroll
    for (int i = 0; i < 8; i++) {
        int f4 = tid + i * 256;
        int r = f4 >> 4, c4 = f4 & 15;
        int qi = q0 + r;
        float4 qv = make_float4(0.f, 0.f, 0.f, 0.f);
        if (qi < T_LEN) qv = *(const float4*)&g_q[base + (size_t)qi * H_DIM + c4 * 4];
        qv.x *= 0.125f; qv.y *= 0.125f; qv.z *= 0.125f; qv.w *= 0.125f;
        *(float4*)&q_s[r * QS + c4 * 4] = qv;
    }
    __syncthreads();

    // per-q-row augmentation params (alpha pre-scaled by 0.125)
    if (tid < QT) {
        int r = tid;
        int qi = q0 + r;
        if (qi >= 1 && qi < T_LEN) {
            float a = 0.f, s0 = 0.f, s1 = 0.f;
#pragma unroll 8
            for (int c = 0; c < 64; c++) {
                float qv = q_s[r * QS + c] * 8.f;
                a  += qv * w_alpha[c];
                s0 += qv * w_sigma[c * 2 + 0];
                s1 += qv * w_sigma[c * 2 + 1];
            }
            a += b_alpha[0]; s0 += b_sigma[0]; s1 += b_sigma[1];
            float alpha = fmaxf(a, 0.f) + log1pf(expf(-fabsf(a)));
            float sx = 1.f / (1.f + expf(-s0));
            float sy = 1.f / (1.f + expf(-s1));
            al_s[r] = alpha * 0.125f;
            ix_s[r] = 0.5f / (sx * sx);
            iy_s[r] = 0.5f / (sy * sy);
            int gq = qi - 1;
            gx_s[r] = (float)(gq % GW);
            gy_s[r] = (float)(gq / GW);
        } else {
            al_s[r] = 0.f; ix_s[r] = 0.f; iy_s[r] = 0.f;
            gx_s[r] = 0.f; gy_s[r] = 0.f;
        }
    }
    __syncthreads();

    float m_i[8], l_i[8];
#pragma unroll
    for (int iq = 0; iq < 8; iq++) { m_i[iq] = -1e30f; l_i[iq] = 0.f; }

    float oacc[8][4];
#pragma unroll
    for (int i = 0; i < 8; i++)
#pragma unroll
        for (int j = 0; j < 4; j++) oacc[i][j] = 0.f;

    for (int k0 = 0; k0 < T_LEN; k0 += KT) {
        // load K/V tile (64 rows x 64 cols, float4, coalesced)
#pragma unroll
        for (int i = 0; i < 4; i++) {
            int f4 = tid + i * 256;                 // 0..1023
            int r = f4 >> 4, c4 = f4 & 15;
            int ki = k0 + r;
            float4 kv = make_float4(0.f, 0.f, 0.f, 0.f);
            float4 vv = kv;
            if (ki < T_LEN) {
                kv = *(const float4*)&g_k[base + (size_t)ki * H_DIM + c4 * 4];
                vv = *(const float4*)&g_v[base + (size_t)ki * H_DIM + c4 * 4];
            }
            *(float4*)&k_s[r * QS + c4 * 4] = kv;
            *(float4*)&v_s[r * QS + c4 * 4] = vv;
        }
        __syncthreads();

        // sim: 8q x 4k per thread (k strided tx + 16*ik)
        float s[8][4];
#pragma unroll
        for (int i = 0; i < 8; i++)
#pragma unroll
            for (int j = 0; j < 4; j++) s[i][j] = 0.f;

#pragma unroll 2
        for (int j4 = 0; j4 < 16; j4++) {
            float4 kv[4];
#pragma unroll
            for (int j = 0; j < 4; j++)
                kv[j] = *(const float4*)&k_s[(tx + 16 * j) * QS + j4 * 4];
#pragma unroll
            for (int iq = 0; iq < 8; iq++) {
                float4 qv = *(const float4*)&q_s[(ty * 8 + iq) * QS + j4 * 4];
#pragma unroll
                for (int ik = 0; ik < 4; ik++)
                    s[iq][ik] += qv.x * kv[ik].x + qv.y * kv[ik].y +
                                 qv.z * kv[ik].z + qv.w * kv[ik].w;
            }
        }

        // Gaussian augmentation + mask (params from smem per iq)
#pragma unroll
        for (int iq = 0; iq < 8; iq++) {
            int r = ty * 8 + iq;
            float alr = al_s[r], ixr = ix_s[r], iyr = iy_s[r];
            float qgx = gx_s[r], qgy = gy_s[r];
#pragma unroll
            for (int ik = 0; ik < 4; ik++) {
                int ki = k0 + tx + 16 * ik;
                bool kvalid = (ki < T_LEN);
                bool kaug = (ki >= 1) && kvalid;
                int g = kaug ? ki - 1 : 0;
                float kgx = (float)(g % GW);
                float kgy = (float)(g / GW);
                float val = s[iq][ik];
                if (kaug) {
                    float dgx = qgx - kgx;
                    float dgy = qgy - kgy;
                    val += alr * __expf(-dgx * dgx * ixr - dgy * dgy * iyr);
                }
                if (!kvalid) val = -1e30f;
                s[iq][ik] = val;
            }
        }

        // register softmax over 16 tx lanes
        float mloc[8];
#pragma unroll
        for (int iq = 0; iq < 8; iq++)
            mloc[iq] = fmaxf(fmaxf(s[iq][0], s[iq][1]), fmaxf(s[iq][2], s[iq][3]));
#pragma unroll
        for (int o = 8; o >= 1; o >>= 1)
#pragma unroll
            for (int iq = 0; iq < 8; iq++)
                mloc[iq] = fmaxf(mloc[iq], __shfl_xor_sync(0xffffffffu, mloc[iq], o));

        float rs[8];
#pragma unroll
        for (int iq = 0; iq < 8; iq++) {
            float mnew = fmaxf(m_i[iq], mloc[iq]);
            float scf = __expf(m_i[iq] - mnew);
            m_i[iq] = mnew;
            float sum = 0.f;
#pragma unroll
            for (int ik = 0; ik < 4; ik++) {
                float p = __expf(s[iq][ik] - mnew);
                s[iq][ik] = p;
                sum += p;
            }
            rs[iq] = sum;
            l_i[iq] *= scf;
#pragma unroll
            for (int ih = 0; ih < 4; ih++) oacc[iq][ih] *= scf;
        }
#pragma unroll
        for (int o = 8; o >= 1; o >>= 1)
#pragma unroll
            for (int iq = 0; iq < 8; iq++)
                rs[iq] += __shfl_xor_sync(0xffffffffu, rs[iq], o);
#pragma unroll
        for (int iq = 0; iq < 8; iq++) l_i[iq] += rs[iq];

        // stage P (exp'd) to smem at strided k positions
#pragma unroll
        for (int iq = 0; iq < 8; iq++)
#pragma unroll
            for (int ik = 0; ik < 4; ik++)
                p_s[(ty * 8 + iq) * QS + tx + 16 * ik] = s[iq][ik];
        __syncthreads();

        // P @ V: 8q x 4h per thread, k = 64
#pragma unroll 2
        for (int kc4 = 0; kc4 < KT / 4; kc4++) {
            float4 vv[4];
#pragma unroll
            for (int j = 0; j < 4; j++)
                vv[j] = *(const float4*)&v_s[(kc4 * 4 + j) * QS + tx * 4];
#pragma unroll
            for (int iq = 0; iq < 8; iq++) {
                float4 pr = *(const float4*)&p_s[(ty * 8 + iq) * QS + kc4 * 4];
                oacc[iq][0] += pr.x * vv[0].x + pr.y * vv[1].x +
                               pr.z * vv[2].x + pr.w * vv[3].x;
                oacc[iq][1] += pr.x * vv[0].y + pr.y * vv[1].y +
                               pr.z * vv[2].y + pr.w * vv[3].y;
                oacc[iq][2] += pr.x * vv[0].z + pr.y * vv[1].z +
                               pr.z * vv[2].z + pr.w * vv[3].z;
                oacc[iq][3] += pr.x * vv[0].w + pr.y * vv[1].w +
                               pr.z * vv[2].w + pr.w * vv[3].w;
            }
        }
        __syncthreads();
    }

    // final normalize + write
#pragma unroll
    for (int iq = 0; iq < 8; iq++) {
        int r = ty * 8 + iq;
        int qi = q0 + r;
        if (qi < T_LEN) {
            float inv = 1.f / l_i[iq];
            float4 o;
            o.x = oacc[iq][0] * inv;
            o.y = oacc[iq][1] * inv;
            o.z = oacc[iq][2] * inv;
            o.w = oacc[iq][3] * inv;
            *(float4*)&out[base + (size_t)qi * H_DIM + tx * 4] = o;
        }
    }
}

// ---------------------------------------------------------------------------
extern "C" void kernel_launch(void* const* d_in, const int* in_sizes, int n_in,
                              void* d_out, int out_size)
{
    const float* x       = (const float*)d_in[0];
    const float* w_q     = (const float*)d_in[1];
    const float* w_k     = (const float*)d_in[2];
    const float* w_v     = (const float*)d_in[3];
    const float* q_gamma = (const float*)d_in[4];
    const float* q_beta  = (const float*)d_in[5];
    const float* k_gamma = (const float*)d_in[6];
    const float* k_beta  = (const float*)d_in[7];
    const float* w_sigma = (const float*)d_in[8];
    const float* b_sigma = (const float*)d_in[9];
    const float* w_alpha = (const float*)d_in[10];
    const float* b_alpha = (const float*)d_in[11];
    float* out = (float*)d_out;

    dim3 grid1((M_ROWS + 127) / 128, 3);
    qkv_ln_kernel<<<grid1, 256>>>(x, w_q, w_k, w_v, q_gamma, q_beta, k_gamma, k_beta);

    cudaFuncSetAttribute(attn_kernel, cudaFuncAttributeMaxDynamicSharedMemorySize,
                         ATTN_SMEM_BYTES);
    dim3 grid2((T_LEN + QT - 1) / QT, B_SZ);
    attn_kernel<<<grid2, 256, ATTN_SMEM_BYTES>>>(w_sigma, b_sigma, w_alpha, b_alpha, out);
}

// round 9
// speedup vs baseline: 1.2887x; 1.2496x over previous
#include <cuda_runtime.h>
#include <cuda_bf16.h>
#include <math.h>
#include <stdint.h>

#define M_ROWS 36928   // B*T = 64*577
#define E_DIM  768
#define H_DIM  64
#define T_LEN  577
#define B_SZ   64
#define GW     24

// scratch (static device arrays; no allocation)
__device__ float g_q[M_ROWS * H_DIM];
__device__ float g_k[M_ROWS * H_DIM];
__device__ float g_v[M_ROWS * H_DIM];
// concatenated transposed weights, split bf16: [n=192][k=768]
__device__ __nv_bfloat16 g_wcat_hi[192 * E_DIM];
__device__ __nv_bfloat16 g_wcat_lo[192 * E_DIM];

__device__ __forceinline__ uint32_t smem_u32(const void* p) {
    uint32_t a;
    asm("{ .reg .u64 t; cvta.to.shared.u64 t, %1; cvt.u32.u64 %0, t; }" : "=r"(a) : "l"(p));
    return a;
}
__device__ __forceinline__ void ldsm_x4(uint32_t* r, uint32_t addr) {
    asm volatile("ldmatrix.sync.aligned.m8n8.x4.shared.b16 {%0,%1,%2,%3}, [%4];"
                 : "=r"(r[0]), "=r"(r[1]), "=r"(r[2]), "=r"(r[3]) : "r"(addr));
}
__device__ __forceinline__ void mma_bf16(float* d, const uint32_t* a, const uint32_t* b) {
    asm volatile(
        "mma.sync.aligned.m16n8k16.row.col.f32.bf16.bf16.f32 "
        "{%0,%1,%2,%3}, {%4,%5,%6,%7}, {%8,%9}, {%0,%1,%2,%3};"
        : "+f"(d[0]), "+f"(d[1]), "+f"(d[2]), "+f"(d[3])
        : "r"(a[0]), "r"(a[1]), "r"(a[2]), "r"(a[3]), "r"(b[0]), "r"(b[1]));
}
__device__ __forceinline__ uint32_t packbf(__nv_bfloat16 a, __nv_bfloat16 b) {
    uint16_t ua = *(uint16_t*)&a, ub = *(uint16_t*)&b;
    return (uint32_t)ua | ((uint32_t)ub << 16);
}

// ---------------------------------------------------------------------------
// Kernel 0: weight prep — wcat[n][k] = w_{q,k,v}[k][n%64], split into bf16 hi/lo
// ---------------------------------------------------------------------------
__global__ void prep_w_kernel(const float* __restrict__ w_q, const float* __restrict__ w_k,
                              const float* __restrict__ w_v)
{
    int idx = blockIdx.x * blockDim.x + threadIdx.x;
    if (idx >= 192 * E_DIM) return;
    int n = idx / E_DIM, k = idx % E_DIM;
    const float* w = (n < 64) ? w_q : (n < 128) ? w_k : w_v;
    float v = w[k * H_DIM + (n & 63)];
    __nv_bfloat16 hi = __float2bfloat16(v);
    __nv_bfloat16 lo = __float2bfloat16(v - __bfloat162float(hi));
    g_wcat_hi[idx] = hi;
    g_wcat_lo[idx] = lo;
}

// ---------------------------------------------------------------------------
// Kernel 1: split-bf16 mma.sync QKV GEMM + fused LayerNorm epilogue
// grid = 577 (M tiles of 64), 256 threads = 8 warps (2M x 4N), warp tile 32x48
// D[64,192] = X[64,768] @ Wcat^T, hi*hi + hi*lo + lo*hi into fp32 acc
// R4 kernel verbatim EXCEPT __launch_bounds__(256) — no min-blocks, no reg cap
// ---------------------------------------------------------------------------
#define GK 64
#define NCHUNK (E_DIM / GK)
#define AS 144                     // smem row stride bytes (72 bf16)
#define SM_A_HI 0
#define SM_A_LO (SM_A_HI + 64 * AS)        //  9216
#define SM_B_HI (SM_A_LO + 64 * AS)        // 18432
#define SM_B_LO (SM_B_HI + 192 * AS)       // 46080
#define SM_TOTAL (SM_B_LO + 192 * AS)      // 73728
#define STG_S 201                  // epilogue stage stride (floats)

__global__ __launch_bounds__(256) void qkv_mma_kernel(
    const float* __restrict__ x,
    const float* __restrict__ q_gamma, const float* __restrict__ q_beta,
    const float* __restrict__ k_gamma, const float* __restrict__ k_beta)
{
    extern __shared__ char smc[];
    const uint32_t sb = smem_u32(smc);
    const int tid  = threadIdx.x;
    const int wid  = tid >> 5;
    const int lane = tid & 31;
    const int wm   = wid >> 2;          // 0..1 -> M offset *32
    const int wn   = wid & 3;           // 0..3 -> N offset *48
    const int m0   = blockIdx.x * 64;

    const uint32_t aOff = (uint32_t)((wm * 32 + (lane & 15)) * AS + (lane >> 4) * 16);
    const uint32_t bOff = (uint32_t)((wn * 48 + ((lane >> 4) << 3) + (lane & 7)) * AS
                                     + ((lane >> 3) & 1) * 16);

    float acc[2][6][4];
#pragma unroll
    for (int i = 0; i < 2; i++)
#pragma unroll
        for (int j = 0; j < 6; j++)
#pragma unroll
            for (int c = 0; c < 4; c++) acc[i][j][c] = 0.f;

    for (int ch = 0; ch < NCHUNK; ch++) {
        const int k0 = ch * GK;
        // A chunk: x fp32 -> bf16 hi/lo (64 rows x 64 cols)
#pragma unroll
        for (int it = 0; it < 4; it++) {
            int i = tid + it * 256;         // 0..1023
            int r = i >> 4, col = (i & 15) * 4;
            float4 v = *(const float4*)&x[(size_t)(m0 + r) * E_DIM + k0 + col];
            __nv_bfloat16 h0 = __float2bfloat16(v.x), h1 = __float2bfloat16(v.y);
            __nv_bfloat16 h2 = __float2bfloat16(v.z), h3 = __float2bfloat16(v.w);
            __nv_bfloat16 l0 = __float2bfloat16(v.x - __bfloat162float(h0));
            __nv_bfloat16 l1 = __float2bfloat16(v.y - __bfloat162float(h1));
            __nv_bfloat16 l2 = __float2bfloat16(v.z - __bfloat162float(h2));
            __nv_bfloat16 l3 = __float2bfloat16(v.w - __bfloat162float(h3));
            uint32_t off = (uint32_t)(r * AS + col * 2);
            *(uint2*)(smc + SM_A_HI + off) = make_uint2(packbf(h0, h1), packbf(h2, h3));
            *(uint2*)(smc + SM_A_LO + off) = make_uint2(packbf(l0, l1), packbf(l2, l3));
        }
        // B chunk: pre-split bf16 (192 rows x 64 cols)
#pragma unroll
        for (int it = 0; it < 12; it++) {
            int i = tid + it * 256;         // 0..3071
            int r = i >> 4, col = (i & 15) * 4;
            size_t src = (size_t)r * E_DIM + k0 + col;
            uint32_t off = (uint32_t)(r * AS + col * 2);
            *(uint2*)(smc + SM_B_HI + off) = *(const uint2*)&g_wcat_hi[src];
            *(uint2*)(smc + SM_B_LO + off) = *(const uint2*)&g_wcat_lo[src];
        }
        __syncthreads();

#pragma unroll
        for (int ks = 0; ks < 4; ks++) {
            const uint32_t kb = (uint32_t)(ks * 32);
            uint32_t ahi[2][4], alo[2][4];
#pragma unroll
            for (int im = 0; im < 2; im++) {
                ldsm_x4(ahi[im], sb + SM_A_HI + aOff + im * 16 * AS + kb);
                ldsm_x4(alo[im], sb + SM_A_LO + aOff + im * 16 * AS + kb);
            }
            uint32_t bhi[6][2], blo[6][2];
#pragma unroll
            for (int j = 0; j < 3; j++) {
                uint32_t t[4];
                ldsm_x4(t, sb + SM_B_HI + bOff + j * 16 * AS + kb);
                bhi[2 * j][0] = t[0]; bhi[2 * j][1] = t[1];
                bhi[2 * j + 1][0] = t[2]; bhi[2 * j + 1][1] = t[3];
                ldsm_x4(t, sb + SM_B_LO + bOff + j * 16 * AS + kb);
                blo[2 * j][0] = t[0]; blo[2 * j][1] = t[1];
                blo[2 * j + 1][0] = t[2]; blo[2 * j + 1][1] = t[3];
            }
#pragma unroll
            for (int im = 0; im < 2; im++)
#pragma unroll
                for (int jn = 0; jn < 6; jn++) {
                    mma_bf16(acc[im][jn], ahi[im], bhi[jn]);
                    mma_bf16(acc[im][jn], ahi[im], blo[jn]);
                    mma_bf16(acc[im][jn], alo[im], bhi[jn]);
                }
        }
        __syncthreads();
    }

    // stage accumulators to smem: [64 rows][192 cols] fp32, stride STG_S
    float* stage = (float*)smc;
#pragma unroll
    for (int im = 0; im < 2; im++)
#pragma unroll
        for (int jn = 0; jn < 6; jn++) {
            int row = wm * 32 + im * 16 + (lane >> 2);
            int col = wn * 48 + jn * 8 + (lane & 3) * 2;
            stage[row * STG_S + col]           = acc[im][jn][0];
            stage[row * STG_S + col + 1]       = acc[im][jn][1];
            stage[(row + 8) * STG_S + col]     = acc[im][jn][2];
            stage[(row + 8) * STG_S + col + 1] = acc[im][jn][3];
        }
    __syncthreads();

    // LayerNorm epilogue: thread t<192 -> row = t&63, segment = t>>6
    if (tid < 192) {
        int row = tid & 63;
        int seg = tid >> 6;
        float f[64];
#pragma unroll
        for (int c = 0; c < 64; c++) f[c] = stage[row * STG_S + seg * 64 + c];
        if (seg < 2) {
            const float* gamma = (seg == 0) ? q_gamma : k_gamma;
            const float* beta  = (seg == 0) ? q_beta  : k_beta;
            float s = 0.f;
#pragma unroll
            for (int c = 0; c < 64; c++) s += f[c];
            float mu = s * (1.f / 64.f);
            float v2 = 0.f;
#pragma unroll
            for (int c = 0; c < 64; c++) { float d = f[c] - mu; v2 += d * d; }
            float rstd = rsqrtf(v2 * (1.f / 64.f) + 1e-5f);
#pragma unroll
            for (int c = 0; c < 64; c++) f[c] = (f[c] - mu) * rstd * gamma[c] + beta[c];
        }
        float* outg = (seg == 0) ? g_q : (seg == 1) ? g_k : g_v;
        size_t dst = (size_t)(m0 + row) * H_DIM;
#pragma unroll
        for (int c4 = 0; c4 < 16; c4++)
            *(float4*)&outg[dst + c4 * 4] =
                make_float4(f[c4 * 4], f[c4 * 4 + 1], f[c4 * 4 + 2], f[c4 * 4 + 3]);
    }
}

// ---------------------------------------------------------------------------
// Kernel 2 (v5, unchanged from R7): flash attention, QT=128 KT=64, 2 CTAs/SM
// ---------------------------------------------------------------------------
#define QT 128
#define KT 64
#define QS 68
#define ATTN_SMEM_FLOATS (QT*QS + KT*QS + KT*QS + QT*QS + 5*QT)
#define ATTN_SMEM_BYTES  (ATTN_SMEM_FLOATS * 4)

__global__ __launch_bounds__(256, 2) void attn_kernel(
    const float* __restrict__ w_sigma, const float* __restrict__ b_sigma,
    const float* __restrict__ w_alpha, const float* __restrict__ b_alpha,
    float* __restrict__ out)
{
    extern __shared__ float smf[];
    float* q_s  = smf;
    float* k_s  = q_s + QT * QS;
    float* v_s  = k_s + KT * QS;
    float* p_s  = v_s + KT * QS;
    float* al_s = p_s + QT * QS;
    float* ix_s = al_s + QT;
    float* iy_s = ix_s + QT;
    float* gx_s = iy_s + QT;
    float* gy_s = gx_s + QT;

    const int b   = blockIdx.y;
    const int q0  = blockIdx.x * QT;
    const int tid = threadIdx.x;
    const int ty  = tid >> 4, tx = tid & 15;
    const size_t base = (size_t)b * T_LEN * H_DIM;

#pragma unroll
    for (int i = 0; i < 8; i++) {
        int f4 = tid + i * 256;
        int r = f4 >> 4, c4 = f4 & 15;
        int qi = q0 + r;
        float4 qv = make_float4(0.f, 0.f, 0.f, 0.f);
        if (qi < T_LEN) qv = *(const float4*)&g_q[base + (size_t)qi * H_DIM + c4 * 4];
        qv.x *= 0.125f; qv.y *= 0.125f; qv.z *= 0.125f; qv.w *= 0.125f;
        *(float4*)&q_s[r * QS + c4 * 4] = qv;
    }
    __syncthreads();

    if (tid < QT) {
        int r = tid;
        int qi = q0 + r;
        if (qi >= 1 && qi < T_LEN) {
            float a = 0.f, s0 = 0.f, s1 = 0.f;
#pragma unroll 8
            for (int c = 0; c < 64; c++) {
                float qv = q_s[r * QS + c] * 8.f;
                a  += qv * w_alpha[c];
                s0 += qv * w_sigma[c * 2 + 0];
                s1 += qv * w_sigma[c * 2 + 1];
            }
            a += b_alpha[0]; s0 += b_sigma[0]; s1 += b_sigma[1];
            float alpha = fmaxf(a, 0.f) + log1pf(expf(-fabsf(a)));
            float sx = 1.f / (1.f + expf(-s0));
            float sy = 1.f / (1.f + expf(-s1));
            al_s[r] = alpha * 0.125f;
            ix_s[r] = 0.5f / (sx * sx);
            iy_s[r] = 0.5f / (sy * sy);
            int gq = qi - 1;
            gx_s[r] = (float)(gq % GW);
            gy_s[r] = (float)(gq / GW);
        } else {
            al_s[r] = 0.f; ix_s[r] = 0.f; iy_s[r] = 0.f;
            gx_s[r] = 0.f; gy_s[r] = 0.f;
        }
    }
    __syncthreads();

    float m_i[8], l_i[8];
#pragma unroll
    for (int iq = 0; iq < 8; iq++) { m_i[iq] = -1e30f; l_i[iq] = 0.f; }

    float oacc[8][4];
#pragma unroll
    for (int i = 0; i < 8; i++)
#pragma unroll
        for (int j = 0; j < 4; j++) oacc[i][j] = 0.f;

    for (int k0 = 0; k0 < T_LEN; k0 += KT) {
#pragma unroll
        for (int i = 0; i < 4; i++) {
            int f4 = tid + i * 256;
            int r = f4 >> 4, c4 = f4 & 15;
            int ki = k0 + r;
            float4 kv = make_float4(0.f, 0.f, 0.f, 0.f);
            float4 vv = kv;
            if (ki < T_LEN) {
                kv = *(const float4*)&g_k[base + (size_t)ki * H_DIM + c4 * 4];
                vv = *(const float4*)&g_v[base + (size_t)ki * H_DIM + c4 * 4];
            }
            *(float4*)&k_s[r * QS + c4 * 4] = kv;
            *(float4*)&v_s[r * QS + c4 * 4] = vv;
        }
        __syncthreads();

        float s[8][4];
#pragma unroll
        for (int i = 0; i < 8; i++)
#pragma unroll
            for (int j = 0; j < 4; j++) s[i][j] = 0.f;

#pragma unroll 2
        for (int j4 = 0; j4 < 16; j4++) {
            float4 kv[4];
#pragma unroll
            for (int j = 0; j < 4; j++)
                kv[j] = *(const float4*)&k_s[(tx + 16 * j) * QS + j4 * 4];
#pragma unroll
            for (int iq = 0; iq < 8; iq++) {
                float4 qv = *(const float4*)&q_s[(ty * 8 + iq) * QS + j4 * 4];
#pragma unroll
                for (int ik = 0; ik < 4; ik++)
                    s[iq][ik] += qv.x * kv[ik].x + qv.y * kv[ik].y +
                                 qv.z * kv[ik].z + qv.w * kv[ik].w;
            }
        }

#pragma unroll
        for (int iq = 0; iq < 8; iq++) {
            int r = ty * 8 + iq;
            float alr = al_s[r], ixr = ix_s[r], iyr = iy_s[r];
            float qgx = gx_s[r], qgy = gy_s[r];
#pragma unroll
            for (int ik = 0; ik < 4; ik++) {
                int ki = k0 + tx + 16 * ik;
                bool kvalid = (ki < T_LEN);
                bool kaug = (ki >= 1) && kvalid;
                int g = kaug ? ki - 1 : 0;
                float kgx = (float)(g % GW);
                float kgy = (float)(g / GW);
                float val = s[iq][ik];
                if (kaug) {
                    float dgx = qgx - kgx;
                    float dgy = qgy - kgy;
                    val += alr * __expf(-dgx * dgx * ixr - dgy * dgy * iyr);
                }
                if (!kvalid) val = -1e30f;
                s[iq][ik] = val;
            }
        }

        float mloc[8];
#pragma unroll
        for (int iq = 0; iq < 8; iq++)
            mloc[iq] = fmaxf(fmaxf(s[iq][0], s[iq][1]), fmaxf(s[iq][2], s[iq][3]));
#pragma unroll
        for (int o = 8; o >= 1; o >>= 1)
#pragma unroll
            for (int iq = 0; iq < 8; iq++)
                mloc[iq] = fmaxf(mloc[iq], __shfl_xor_sync(0xffffffffu, mloc[iq], o));

        float rs[8];
#pragma unroll
        for (int iq = 0; iq < 8; iq++) {
            float mnew = fmaxf(m_i[iq], mloc[iq]);
            float scf = __expf(m_i[iq] - mnew);
            m_i[iq] = mnew;
            float sum = 0.f;
#pragma unroll
            for (int ik = 0; ik < 4; ik++) {
                float p = __expf(s[iq][ik] - mnew);
                s[iq][ik] = p;
                sum += p;
            }
            rs[iq] = sum;
            l_i[iq] *= scf;
#pragma unroll
            for (int ih = 0; ih < 4; ih++) oacc[iq][ih] *= scf;
        }
#pragma unroll
        for (int o = 8; o >= 1; o >>= 1)
#pragma unroll
            for (int iq = 0; iq < 8; iq++)
                rs[iq] += __shfl_xor_sync(0xffffffffu, rs[iq], o);
#pragma unroll
        for (int iq = 0; iq < 8; iq++) l_i[iq] += rs[iq];

#pragma unroll
        for (int iq = 0; iq < 8; iq++)
#pragma unroll
            for (int ik = 0; ik < 4; ik++)
                p_s[(ty * 8 + iq) * QS + tx + 16 * ik] = s[iq][ik];
        __syncthreads();

#pragma unroll 2
        for (int kc4 = 0; kc4 < KT / 4; kc4++) {
            float4 vv[4];
#pragma unroll
            for (int j = 0; j < 4; j++)
                vv[j] = *(const float4*)&v_s[(kc4 * 4 + j) * QS + tx * 4];
#pragma unroll
            for (int iq = 0; iq < 8; iq++) {
                float4 pr = *(const float4*)&p_s[(ty * 8 + iq) * QS + kc4 * 4];
                oacc[iq][0] += pr.x * vv[0].x + pr.y * vv[1].x +
                               pr.z * vv[2].x + pr.w * vv[3].x;
                oacc[iq][1] += pr.x * vv[0].y + pr.y * vv[1].y +
                               pr.z * vv[2].y + pr.w * vv[3].y;
                oacc[iq][2] += pr.x * vv[0].z + pr.y * vv[1].z +
                               pr.z * vv[2].z + pr.w * vv[3].z;
                oacc[iq][3] += pr.x * vv[0].w + pr.y * vv[1].w +
                               pr.z * vv[2].w + pr.w * vv[3].w;
            }
        }
        __syncthreads();
    }

#pragma unroll
    for (int iq = 0; iq < 8; iq++) {
        int r = ty * 8 + iq;
        int qi = q0 + r;
        if (qi < T_LEN) {
            float inv = 1.f / l_i[iq];
            float4 o;
            o.x = oacc[iq][0] * inv;
            o.y = oacc[iq][1] * inv;
            o.z = oacc[iq][2] * inv;
            o.w = oacc[iq][3] * inv;
            *(float4*)&out[base + (size_t)qi * H_DIM + tx * 4] = o;
        }
    }
}

// ---------------------------------------------------------------------------
extern "C" void kernel_launch(void* const* d_in, const int* in_sizes, int n_in,
                              void* d_out, int out_size)
{
    const float* x       = (const float*)d_in[0];
    const float* w_q     = (const float*)d_in[1];
    const float* w_k     = (const float*)d_in[2];
    const float* w_v     = (const float*)d_in[3];
    const float* q_gamma = (const float*)d_in[4];
    const float* q_beta  = (const float*)d_in[5];
    const float* k_gamma = (const float*)d_in[6];
    const float* k_beta  = (const float*)d_in[7];
    const float* w_sigma = (const float*)d_in[8];
    const float* b_sigma = (const float*)d_in[9];
    const float* w_alpha = (const float*)d_in[10];
    const float* b_alpha = (const float*)d_in[11];
    float* out = (float*)d_out;

    prep_w_kernel<<<(192 * E_DIM + 255) / 256, 256>>>(w_q, w_k, w_v);

    cudaFuncSetAttribute(qkv_mma_kernel, cudaFuncAttributeMaxDynamicSharedMemorySize, SM_TOTAL);
    qkv_mma_kernel<<<M_ROWS / 64, 256, SM_TOTAL>>>(x, q_gamma, q_beta, k_gamma, k_beta);

    cudaFuncSetAttribute(attn_kernel, cudaFuncAttributeMaxDynamicSharedMemorySize, ATTN_SMEM_BYTES);
    dim3 grid2((T_LEN + QT - 1) / QT, B_SZ);
    attn_kernel<<<grid2, 256, ATTN_SMEM_BYTES>>>(w_sigma, b_sigma, w_alpha, b_alpha, out);
}

// round 10
// speedup vs baseline: 1.9722x; 1.5304x over previous
#include <cuda_runtime.h>
#include <cuda_bf16.h>
#include <math.h>
#include <stdint.h>

#define M_ROWS 36928   // B*T = 64*577
#define E_DIM  768
#define H_DIM  64
#define T_LEN  577
#define B_SZ   64
#define GW     24

// scratch (static device arrays; no allocation)
__device__ float g_q[M_ROWS * H_DIM];
__device__ float g_k[M_ROWS * H_DIM];
__device__ float g_v[M_ROWS * H_DIM];
// concatenated transposed weights, split bf16: [n=192][k=768]
__device__ __nv_bfloat16 g_wcat_hi[192 * E_DIM];
__device__ __nv_bfloat16 g_wcat_lo[192 * E_DIM];

__device__ __forceinline__ uint32_t smem_u32(const void* p) {
    uint32_t a;
    asm("{ .reg .u64 t; cvta.to.shared.u64 t, %1; cvt.u32.u64 %0, t; }" : "=r"(a) : "l"(p));
    return a;
}
__device__ __forceinline__ void ldsm_x4(uint32_t* r, uint32_t addr) {
    asm volatile("ldmatrix.sync.aligned.m8n8.x4.shared.b16 {%0,%1,%2,%3}, [%4];"
                 : "=r"(r[0]), "=r"(r[1]), "=r"(r[2]), "=r"(r[3]) : "r"(addr));
}
__device__ __forceinline__ void mma_bf16(float* d, const uint32_t* a, const uint32_t* b) {
    asm volatile(
        "mma.sync.aligned.m16n8k16.row.col.f32.bf16.bf16.f32 "
        "{%0,%1,%2,%3}, {%4,%5,%6,%7}, {%8,%9}, {%0,%1,%2,%3};"
        : "+f"(d[0]), "+f"(d[1]), "+f"(d[2]), "+f"(d[3])
        : "r"(a[0]), "r"(a[1]), "r"(a[2]), "r"(a[3]), "r"(b[0]), "r"(b[1]));
}
__device__ __forceinline__ uint32_t packbf(__nv_bfloat16 a, __nv_bfloat16 b) {
    uint16_t ua = *(uint16_t*)&a, ub = *(uint16_t*)&b;
    return (uint32_t)ua | ((uint32_t)ub << 16);
}
// pack two fp32 -> bf16x2, lo in low half (matches A-frag: even col low)
__device__ __forceinline__ uint32_t pk_bf2(float lo, float hi) {
    uint32_t r; asm("cvt.rn.bf16x2.f32 %0, %1, %2;" : "=r"(r) : "f"(hi), "f"(lo)); return r;
}

// ---------------------------------------------------------------------------
// Kernel 0: weight prep
// ---------------------------------------------------------------------------
__global__ void prep_w_kernel(const float* __restrict__ w_q, const float* __restrict__ w_k,
                              const float* __restrict__ w_v)
{
    int idx = blockIdx.x * blockDim.x + threadIdx.x;
    if (idx >= 192 * E_DIM) return;
    int n = idx / E_DIM, k = idx % E_DIM;
    const float* w = (n < 64) ? w_q : (n < 128) ? w_k : w_v;
    float v = w[k * H_DIM + (n & 63)];
    __nv_bfloat16 hi = __float2bfloat16(v);
    __nv_bfloat16 lo = __float2bfloat16(v - __bfloat162float(hi));
    g_wcat_hi[idx] = hi;
    g_wcat_lo[idx] = lo;
}

// ---------------------------------------------------------------------------
// Kernel 1: split-bf16 mma.sync QKV GEMM + LayerNorm (R9, unchanged)
// ---------------------------------------------------------------------------
#define GK 64
#define NCHUNK (E_DIM / GK)
#define AS 144
#define SM_A_HI 0
#define SM_A_LO (SM_A_HI + 64 * AS)
#define SM_B_HI (SM_A_LO + 64 * AS)
#define SM_B_LO (SM_B_HI + 192 * AS)
#define SM_TOTAL (SM_B_LO + 192 * AS)
#define STG_S 201

__global__ __launch_bounds__(256) void qkv_mma_kernel(
    const float* __restrict__ x,
    const float* __restrict__ q_gamma, const float* __restrict__ q_beta,
    const float* __restrict__ k_gamma, const float* __restrict__ k_beta)
{
    extern __shared__ char smc[];
    const uint32_t sb = smem_u32(smc);
    const int tid  = threadIdx.x;
    const int wid  = tid >> 5;
    const int lane = tid & 31;
    const int wm   = wid >> 2;
    const int wn   = wid & 3;
    const int m0   = blockIdx.x * 64;

    const uint32_t aOff = (uint32_t)((wm * 32 + (lane & 15)) * AS + (lane >> 4) * 16);
    const uint32_t bOff = (uint32_t)((wn * 48 + ((lane >> 4) << 3) + (lane & 7)) * AS
                                     + ((lane >> 3) & 1) * 16);

    float acc[2][6][4];
#pragma unroll
    for (int i = 0; i < 2; i++)
#pragma unroll
        for (int j = 0; j < 6; j++)
#pragma unroll
            for (int c = 0; c < 4; c++) acc[i][j][c] = 0.f;

    for (int ch = 0; ch < NCHUNK; ch++) {
        const int k0 = ch * GK;
#pragma unroll
        for (int it = 0; it < 4; it++) {
            int i = tid + it * 256;
            int r = i >> 4, col = (i & 15) * 4;
            float4 v = *(const float4*)&x[(size_t)(m0 + r) * E_DIM + k0 + col];
            __nv_bfloat16 h0 = __float2bfloat16(v.x), h1 = __float2bfloat16(v.y);
            __nv_bfloat16 h2 = __float2bfloat16(v.z), h3 = __float2bfloat16(v.w);
            __nv_bfloat16 l0 = __float2bfloat16(v.x - __bfloat162float(h0));
            __nv_bfloat16 l1 = __float2bfloat16(v.y - __bfloat162float(h1));
            __nv_bfloat16 l2 = __float2bfloat16(v.z - __bfloat162float(h2));
            __nv_bfloat16 l3 = __float2bfloat16(v.w - __bfloat162float(h3));
            uint32_t off = (uint32_t)(r * AS + col * 2);
            *(uint2*)(smc + SM_A_HI + off) = make_uint2(packbf(h0, h1), packbf(h2, h3));
            *(uint2*)(smc + SM_A_LO + off) = make_uint2(packbf(l0, l1), packbf(l2, l3));
        }
#pragma unroll
        for (int it = 0; it < 12; it++) {
            int i = tid + it * 256;
            int r = i >> 4, col = (i & 15) * 4;
            size_t src = (size_t)r * E_DIM + k0 + col;
            uint32_t off = (uint32_t)(r * AS + col * 2);
            *(uint2*)(smc + SM_B_HI + off) = *(const uint2*)&g_wcat_hi[src];
            *(uint2*)(smc + SM_B_LO + off) = *(const uint2*)&g_wcat_lo[src];
        }
        __syncthreads();

#pragma unroll
        for (int ks = 0; ks < 4; ks++) {
            const uint32_t kb = (uint32_t)(ks * 32);
            uint32_t ahi[2][4], alo[2][4];
#pragma unroll
            for (int im = 0; im < 2; im++) {
                ldsm_x4(ahi[im], sb + SM_A_HI + aOff + im * 16 * AS + kb);
                ldsm_x4(alo[im], sb + SM_A_LO + aOff + im * 16 * AS + kb);
            }
            uint32_t bhi[6][2], blo[6][2];
#pragma unroll
            for (int j = 0; j < 3; j++) {
                uint32_t t[4];
                ldsm_x4(t, sb + SM_B_HI + bOff + j * 16 * AS + kb);
                bhi[2 * j][0] = t[0]; bhi[2 * j][1] = t[1];
                bhi[2 * j + 1][0] = t[2]; bhi[2 * j + 1][1] = t[3];
                ldsm_x4(t, sb + SM_B_LO + bOff + j * 16 * AS + kb);
                blo[2 * j][0] = t[0]; blo[2 * j][1] = t[1];
                blo[2 * j + 1][0] = t[2]; blo[2 * j + 1][1] = t[3];
            }
#pragma unroll
            for (int im = 0; im < 2; im++)
#pragma unroll
                for (int jn = 0; jn < 6; jn++) {
                    mma_bf16(acc[im][jn], ahi[im], bhi[jn]);
                    mma_bf16(acc[im][jn], ahi[im], blo[jn]);
                    mma_bf16(acc[im][jn], alo[im], bhi[jn]);
                }
        }
        __syncthreads();
    }

    float* stage = (float*)smc;
#pragma unroll
    for (int im = 0; im < 2; im++)
#pragma unroll
        for (int jn = 0; jn < 6; jn++) {
            int row = wm * 32 + im * 16 + (lane >> 2);
            int col = wn * 48 + jn * 8 + (lane & 3) * 2;
            stage[row * STG_S + col]           = acc[im][jn][0];
            stage[row * STG_S + col + 1]       = acc[im][jn][1];
            stage[(row + 8) * STG_S + col]     = acc[im][jn][2];
            stage[(row + 8) * STG_S + col + 1] = acc[im][jn][3];
        }
    __syncthreads();

    if (tid < 192) {
        int row = tid & 63;
        int seg = tid >> 6;
        float f[64];
#pragma unroll
        for (int c = 0; c < 64; c++) f[c] = stage[row * STG_S + seg * 64 + c];
        if (seg < 2) {
            const float* gamma = (seg == 0) ? q_gamma : k_gamma;
            const float* beta  = (seg == 0) ? q_beta  : k_beta;
            float s = 0.f;
#pragma unroll
            for (int c = 0; c < 64; c++) s += f[c];
            float mu = s * (1.f / 64.f);
            float v2 = 0.f;
#pragma unroll
            for (int c = 0; c < 64; c++) { float d = f[c] - mu; v2 += d * d; }
            float rstd = rsqrtf(v2 * (1.f / 64.f) + 1e-5f);
#pragma unroll
            for (int c = 0; c < 64; c++) f[c] = (f[c] - mu) * rstd * gamma[c] + beta[c];
        }
        float* outg = (seg == 0) ? g_q : (seg == 1) ? g_k : g_v;
        size_t dst = (size_t)(m0 + row) * H_DIM;
#pragma unroll
        for (int c4 = 0; c4 < 16; c4++)
            *(float4*)&outg[dst + c4 * 4] =
                make_float4(f[c4 * 4], f[c4 * 4 + 1], f[c4 * 4 + 2], f[c4 * 4 + 3]);
    }
}

// ---------------------------------------------------------------------------
// Kernel 2 (v7): mma.sync flash attention with fused Gaussian augmentation
// 8 warps, QT=128 (warp w owns q rows 16w..16w+15), KT=64, 10 k-tiles
// sim: split-bf16 Q@K^T (3 MMA); softmax+aug on C frags; FA2 P repack;
// PV: Phi*Vhi + Phi*Vlo + Plo*Vhi against transposed V in smem.
// ---------------------------------------------------------------------------
#define KT 64
#define NKT 10
#define A_QHI 0
#define A_QLO (A_QHI + 128 * AS)      // 18432
#define A_KHI (A_QLO + 128 * AS)      // 36864
#define A_KLO (A_KHI + 64 * AS)       // 46080
#define A_VHI (A_KLO + 64 * AS)       // 55296
#define A_VLO (A_VHI + 64 * AS)       // 64512
#define A_PRM (A_VLO + 64 * AS)       // 73728 (floats from here)
#define A_TOTAL (A_PRM + (5 * 128 + 3 * KT) * 4)

__global__ __launch_bounds__(256) void attn_mma_kernel(
    const float* __restrict__ w_sigma, const float* __restrict__ b_sigma,
    const float* __restrict__ w_alpha, const float* __restrict__ b_alpha,
    float* __restrict__ out)
{
    extern __shared__ char smc[];
    const uint32_t sb = smem_u32(smc);
    float* al_s = (float*)(smc + A_PRM);
    float* ix_s = al_s + 128;
    float* iy_s = ix_s + 128;
    float* gx_s = iy_s + 128;
    float* gy_s = gx_s + 128;
    float* kx_s = gy_s + 128;
    float* ky_s = kx_s + KT;
    float* km_s = ky_s + KT;

    const int tid  = threadIdx.x;
    const int lane = tid & 31;
    const int wid  = tid >> 5;
    const int b    = blockIdx.y;
    const int q0   = blockIdx.x * 128;
    const size_t base = (size_t)b * T_LEN * H_DIM;

    // ---- load Q (fold 0.125 = 1/sqrt(H)), split bf16 hi/lo ----
#pragma unroll
    for (int it = 0; it < 8; it++) {
        int i = tid + it * 256;              // 0..2047
        int r = i >> 4, c4 = i & 15;
        int qi = q0 + r;
        float4 v = make_float4(0.f, 0.f, 0.f, 0.f);
        if (qi < T_LEN) v = *(const float4*)&g_q[base + (size_t)qi * H_DIM + c4 * 4];
        v.x *= 0.125f; v.y *= 0.125f; v.z *= 0.125f; v.w *= 0.125f;
        __nv_bfloat16 h0 = __float2bfloat16(v.x), h1 = __float2bfloat16(v.y);
        __nv_bfloat16 h2 = __float2bfloat16(v.z), h3 = __float2bfloat16(v.w);
        __nv_bfloat16 l0 = __float2bfloat16(v.x - __bfloat162float(h0));
        __nv_bfloat16 l1 = __float2bfloat16(v.y - __bfloat162float(h1));
        __nv_bfloat16 l2 = __float2bfloat16(v.z - __bfloat162float(h2));
        __nv_bfloat16 l3 = __float2bfloat16(v.w - __bfloat162float(h3));
        uint32_t off = (uint32_t)(r * AS + c4 * 8);
        *(uint2*)(smc + A_QHI + off) = make_uint2(packbf(h0, h1), packbf(h2, h3));
        *(uint2*)(smc + A_QLO + off) = make_uint2(packbf(l0, l1), packbf(l2, l3));
    }

    // ---- per-q-row aug params (read g_q directly; alpha pre-scaled 0.125) ----
    if (tid < 128) {
        int r = tid;
        int qi = q0 + r;
        if (qi >= 1 && qi < T_LEN) {
            const float* qrow = &g_q[base + (size_t)qi * H_DIM];
            float a = 0.f, s0 = 0.f, s1 = 0.f;
#pragma unroll 8
            for (int c = 0; c < 64; c++) {
                float qv = qrow[c];
                a  += qv * w_alpha[c];
                s0 += qv * w_sigma[c * 2 + 0];
                s1 += qv * w_sigma[c * 2 + 1];
            }
            a += b_alpha[0]; s0 += b_sigma[0]; s1 += b_sigma[1];
            float alpha = fmaxf(a, 0.f) + log1pf(expf(-fabsf(a)));
            float sx = 1.f / (1.f + expf(-s0));
            float sy = 1.f / (1.f + expf(-s1));
            al_s[r] = alpha * 0.125f;
            ix_s[r] = 0.5f / (sx * sx);
            iy_s[r] = 0.5f / (sy * sy);
            int gq = qi - 1;
            gx_s[r] = (float)(gq % GW);
            gy_s[r] = (float)(gq / GW);
        } else {
            al_s[r] = 0.f; ix_s[r] = 0.f; iy_s[r] = 0.f;
            gx_s[r] = 0.f; gy_s[r] = 0.f;
        }
    }
    __syncthreads();

    // ---- Q fragments resident in registers (per warp: rows 16w..16w+15) ----
    uint32_t qh[4][4], ql[4][4];
    {
        uint32_t aOff = (uint32_t)((wid * 16 + (lane & 15)) * AS + (lane >> 4) * 16);
#pragma unroll
        for (int c = 0; c < 4; c++) {
            ldsm_x4(qh[c], sb + A_QHI + aOff + c * 32);
            ldsm_x4(ql[c], sb + A_QLO + aOff + c * 32);
        }
    }

    // per-thread row params (rows r1 = lane>>2, r2 = r1+8 within warp tile)
    const int r1  = lane >> 2;
    const int lr1 = wid * 16 + r1;
    const float al1 = al_s[lr1],     ix1 = ix_s[lr1],     iy1 = iy_s[lr1];
    const float gx1 = gx_s[lr1],     gy1 = gy_s[lr1];
    const float al2 = al_s[lr1 + 8], ix2 = ix_s[lr1 + 8], iy2 = iy_s[lr1 + 8];
    const float gx2 = gx_s[lr1 + 8], gy2 = gy_s[lr1 + 8];

    float m1 = -1e30f, m2 = -1e30f, l1 = 0.f, l2 = 0.f;
    float oacc[8][4];
#pragma unroll
    for (int n = 0; n < 8; n++)
#pragma unroll
        for (int c = 0; c < 4; c++) oacc[n][c] = 0.f;

    for (int kt = 0; kt < NKT; kt++) {
        const int k0 = kt * KT;
        __syncthreads();   // previous tile's smem reads complete

        // ---- load K tile (split bf16) ----
#pragma unroll
        for (int it = 0; it < 4; it++) {
            int i = tid + it * 256;          // 0..1023
            int r = i >> 4, c4 = i & 15;
            int ki = k0 + r;
            float4 v = make_float4(0.f, 0.f, 0.f, 0.f);
            if (ki < T_LEN) v = *(const float4*)&g_k[base + (size_t)ki * H_DIM + c4 * 4];
            __nv_bfloat16 h0 = __float2bfloat16(v.x), h1 = __float2bfloat16(v.y);
            __nv_bfloat16 h2 = __float2bfloat16(v.z), h3 = __float2bfloat16(v.w);
            __nv_bfloat16 l0 = __float2bfloat16(v.x - __bfloat162float(h0));
            __nv_bfloat16 l1b = __float2bfloat16(v.y - __bfloat162float(h1));
            __nv_bfloat16 l2 = __float2bfloat16(v.z - __bfloat162float(h2));
            __nv_bfloat16 l3 = __float2bfloat16(v.w - __bfloat162float(h3));
            uint32_t off = (uint32_t)(r * AS + c4 * 8);
            *(uint2*)(smc + A_KHI + off) = make_uint2(packbf(h0, h1), packbf(h2, h3));
            *(uint2*)(smc + A_KLO + off) = make_uint2(packbf(l0, l1b), packbf(l2, l3));
        }
        // ---- load V tile TRANSPOSED (vT[h][k]), split bf16, paired stores ----
#pragma unroll
        for (int it = 0; it < 2; it++) {
            int s = tid + it * 256;          // 0..511
            int kp = s & 31, h4 = s >> 5;    // k pair 2kp,2kp+1 ; h4 = 0..15
            int ki0 = k0 + 2 * kp;
            float4 va = make_float4(0.f, 0.f, 0.f, 0.f), vb = va;
            if (ki0 < T_LEN)     va = *(const float4*)&g_v[base + (size_t)ki0 * H_DIM + h4 * 4];
            if (ki0 + 1 < T_LEN) vb = *(const float4*)&g_v[base + (size_t)(ki0 + 1) * H_DIM + h4 * 4];
            float a4[4] = {va.x, va.y, va.z, va.w};
            float b4[4] = {vb.x, vb.y, vb.z, vb.w};
#pragma unroll
            for (int j = 0; j < 4; j++) {
                int h = h4 * 4 + j;
                __nv_bfloat16 h0 = __float2bfloat16(a4[j]);
                __nv_bfloat16 h1 = __float2bfloat16(b4[j]);
                __nv_bfloat16 l0 = __float2bfloat16(a4[j] - __bfloat162float(h0));
                __nv_bfloat16 l1b = __float2bfloat16(b4[j] - __bfloat162float(h1));
                uint32_t off = (uint32_t)(h * AS + kp * 4);
                *(uint32_t*)(smc + A_VHI + off) = packbf(h0, h1);
                *(uint32_t*)(smc + A_VLO + off) = packbf(l0, l1b);
            }
        }
        // ---- k-column grid coords + masks ----
        if (tid < KT) {
            int ki = k0 + tid;
            bool kvalid = ki < T_LEN;
            bool kaug = (ki >= 1) && kvalid;
            int g = kaug ? ki - 1 : 0;
            kx_s[tid] = kaug ? (float)(g % GW) : -1e9f;   // sentinel -> exp underflows to 0
            ky_s[tid] = kaug ? (float)(g / GW) : 0.f;
            km_s[tid] = kvalid ? 0.f : -1e30f;
        }
        __syncthreads();

        // ---- sim = Q @ K^T (split bf16, 3 MMA combos) ----
        float sc[8][4];
#pragma unroll
        for (int n = 0; n < 8; n++)
#pragma unroll
            for (int c = 0; c < 4; c++) sc[n][c] = 0.f;

#pragma unroll
        for (int c = 0; c < 4; c++) {
#pragma unroll
            for (int g = 0; g < 4; g++) {
                uint32_t bOff = (uint32_t)((g * 16 + ((lane >> 4) << 3) + (lane & 7)) * AS
                                           + ((lane >> 3) & 1) * 16 + c * 32);
                uint32_t th[4], tl[4];
                ldsm_x4(th, sb + A_KHI + bOff);
                ldsm_x4(tl, sb + A_KLO + bOff);
                mma_bf16(sc[2 * g],     qh[c], th);
                mma_bf16(sc[2 * g],     qh[c], tl);
                mma_bf16(sc[2 * g],     ql[c], th);
                mma_bf16(sc[2 * g + 1], qh[c], th + 2);
                mma_bf16(sc[2 * g + 1], qh[c], tl + 2);
                mma_bf16(sc[2 * g + 1], ql[c], th + 2);
            }
        }

        // ---- Gaussian aug + mask on C fragments ----
#pragma unroll
        for (int n = 0; n < 8; n++) {
            int kc0 = n * 8 + (lane & 3) * 2;
            float kxa = kx_s[kc0],     kya = ky_s[kc0],     kma = km_s[kc0];
            float kxb = kx_s[kc0 + 1], kyb = ky_s[kc0 + 1], kmb = km_s[kc0 + 1];
            float dxa1 = gx1 - kxa, dya1 = gy1 - kya;
            float dxb1 = gx1 - kxb, dyb1 = gy1 - kyb;
            float dxa2 = gx2 - kxa, dya2 = gy2 - kya;
            float dxb2 = gx2 - kxb, dyb2 = gy2 - kyb;
            sc[n][0] += al1 * __expf(-dxa1 * dxa1 * ix1 - dya1 * dya1 * iy1) + kma;
            sc[n][1] += al1 * __expf(-dxb1 * dxb1 * ix1 - dyb1 * dyb1 * iy1) + kmb;
            sc[n][2] += al2 * __expf(-dxa2 * dxa2 * ix2 - dya2 * dya2 * iy2) + kma;
            sc[n][3] += al2 * __expf(-dxb2 * dxb2 * ix2 - dyb2 * dyb2 * iy2) + kmb;
        }

        // ---- online softmax on fragments (reduce over lanes xor 1,2) ----
        float mx1 = -1e30f, mx2 = -1e30f;
#pragma unroll
        for (int n = 0; n < 8; n++) {
            mx1 = fmaxf(mx1, fmaxf(sc[n][0], sc[n][1]));
            mx2 = fmaxf(mx2, fmaxf(sc[n][2], sc[n][3]));
        }
        mx1 = fmaxf(mx1, __shfl_xor_sync(0xffffffffu, mx1, 1));
        mx1 = fmaxf(mx1, __shfl_xor_sync(0xffffffffu, mx1, 2));
        mx2 = fmaxf(mx2, __shfl_xor_sync(0xffffffffu, mx2, 1));
        mx2 = fmaxf(mx2, __shfl_xor_sync(0xffffffffu, mx2, 2));

        float mnew1 = fmaxf(m1, mx1), mnew2 = fmaxf(m2, mx2);
        float scf1 = __expf(m1 - mnew1), scf2 = __expf(m2 - mnew2);
        m1 = mnew1; m2 = mnew2;

        float sum1 = 0.f, sum2 = 0.f;
#pragma unroll
        for (int n = 0; n < 8; n++) {
            float p0 = __expf(sc[n][0] - m1);
            float p1 = __expf(sc[n][1] - m1);
            float p2 = __expf(sc[n][2] - m2);
            float p3 = __expf(sc[n][3] - m2);
            sc[n][0] = p0; sc[n][1] = p1; sc[n][2] = p2; sc[n][3] = p3;
            sum1 += p0 + p1; sum2 += p2 + p3;
        }
        sum1 += __shfl_xor_sync(0xffffffffu, sum1, 1);
        sum1 += __shfl_xor_sync(0xffffffffu, sum1, 2);
        sum2 += __shfl_xor_sync(0xffffffffu, sum2, 1);
        sum2 += __shfl_xor_sync(0xffffffffu, sum2, 2);
        l1 = l1 * scf1 + sum1;
        l2 = l2 * scf2 + sum2;
#pragma unroll
        for (int n = 0; n < 8; n++) {
            oacc[n][0] *= scf1; oacc[n][1] *= scf1;
            oacc[n][2] *= scf2; oacc[n][3] *= scf2;
        }

        // ---- PV: repack P (C->A frags, split hi/lo), MMA against vT ----
#pragma unroll
        for (int c = 0; c < 4; c++) {
            uint32_t ahi[4], alo[4];
#pragma unroll
            for (int t = 0; t < 2; t++) {          // sim ntiles 2c+t
                float p0 = sc[2 * c + t][0], p1 = sc[2 * c + t][1];
                float p2 = sc[2 * c + t][2], p3 = sc[2 * c + t][3];
                uint32_t h01 = pk_bf2(p0, p1);
                uint32_t h23 = pk_bf2(p2, p3);
                float r0 = p0 - __uint_as_float(h01 << 16);
                float r1b = p1 - __uint_as_float(h01 & 0xffff0000u);
                float r2 = p2 - __uint_as_float(h23 << 16);
                float r3 = p3 - __uint_as_float(h23 & 0xffff0000u);
                ahi[2 * t]     = h01;
                ahi[2 * t + 1] = h23;
                alo[2 * t]     = pk_bf2(r0, r1b);
                alo[2 * t + 1] = pk_bf2(r2, r3);
            }
            // A-frag order: a0,a1 = k 0..7 (ntile 2c rows r1/r2); a2,a3 = k 8..15
            uint32_t af_hi[4] = {ahi[0], ahi[1], ahi[2], ahi[3]};
            uint32_t af_lo[4] = {alo[0], alo[1], alo[2], alo[3]};
#pragma unroll
            for (int g = 0; g < 4; g++) {
                uint32_t bOff = (uint32_t)((g * 16 + ((lane >> 4) << 3) + (lane & 7)) * AS
                                           + ((lane >> 3) & 1) * 16 + c * 32);
                uint32_t th[4], tl[4];
                ldsm_x4(th, sb + A_VHI + bOff);
                ldsm_x4(tl, sb + A_VLO + bOff);
                mma_bf16(oacc[2 * g],     af_hi, th);
                mma_bf16(oacc[2 * g],     af_hi, tl);
                mma_bf16(oacc[2 * g],     af_lo, th);
                mma_bf16(oacc[2 * g + 1], af_hi, th + 2);
                mma_bf16(oacc[2 * g + 1], af_hi, tl + 2);
                mma_bf16(oacc[2 * g + 1], af_lo, th + 2);
            }
        }
    }

    // ---- final normalize + write ----
    float inv1 = 1.f / l1, inv2 = 1.f / l2;
    int qi1 = q0 + wid * 16 + r1;
    int qi2 = qi1 + 8;
#pragma unroll
    for (int n = 0; n < 8; n++) {
        int h = n * 8 + (lane & 3) * 2;
        if (qi1 < T_LEN) {
            float2 o = make_float2(oacc[n][0] * inv1, oacc[n][1] * inv1);
            *(float2*)&out[base + (size_t)qi1 * H_DIM + h] = o;
        }
        if (qi2 < T_LEN) {
            float2 o = make_float2(oacc[n][2] * inv2, oacc[n][3] * inv2);
            *(float2*)&out[base + (size_t)qi2 * H_DIM + h] = o;
        }
    }
}

// ---------------------------------------------------------------------------
extern "C" void kernel_launch(void* const* d_in, const int* in_sizes, int n_in,
                              void* d_out, int out_size)
{
    const float* x       = (const float*)d_in[0];
    const float* w_q     = (const float*)d_in[1];
    const float* w_k     = (const float*)d_in[2];
    const float* w_v     = (const float*)d_in[3];
    const float* q_gamma = (const float*)d_in[4];
    const float* q_beta  = (const float*)d_in[5];
    const float* k_gamma = (const float*)d_in[6];
    const float* k_beta  = (const float*)d_in[7];
    const float* w_sigma = (const float*)d_in[8];
    const float* b_sigma = (const float*)d_in[9];
    const float* w_alpha = (const float*)d_in[10];
    const float* b_alpha = (const float*)d_in[11];
    float* out = (float*)d_out;

    prep_w_kernel<<<(192 * E_DIM + 255) / 256, 256>>>(w_q, w_k, w_v);

    cudaFuncSetAttribute(qkv_mma_kernel, cudaFuncAttributeMaxDynamicSharedMemorySize, SM_TOTAL);
    qkv_mma_kernel<<<M_ROWS / 64, 256, SM_TOTAL>>>(x, q_gamma, q_beta, k_gamma, k_beta);

    cudaFuncSetAttribute(attn_mma_kernel, cudaFuncAttributeMaxDynamicSharedMemorySize, A_TOTAL);
    dim3 grid2((T_LEN + 127) / 128, B_SZ);
    attn_mma_kernel<<<grid2, 256, A_TOTAL>>>(w_sigma, b_sigma, w_alpha, b_alpha, out);
}

// round 12
// speedup vs baseline: 2.2767x; 1.1544x over previous
#include <cuda_runtime.h>
#include <cuda_bf16.h>
#include <math.h>
#include <stdint.h>

#define M_ROWS 36928   // B*T = 64*577
#define E_DIM  768
#define H_DIM  64
#define T_LEN  577
#define B_SZ   64
#define GW     24

// scratch (static device arrays; no allocation)
__device__ float g_q[M_ROWS * H_DIM];
__device__ float g_k[M_ROWS * H_DIM];
__device__ float g_v[M_ROWS * H_DIM];
// concatenated transposed weights, split bf16: [n=192][k=768]
__device__ __nv_bfloat16 g_wcat_hi[192 * E_DIM];
__device__ __nv_bfloat16 g_wcat_lo[192 * E_DIM];

__device__ __forceinline__ uint32_t smem_u32(const void* p) {
    uint32_t a;
    asm("{ .reg .u64 t; cvta.to.shared.u64 t, %1; cvt.u32.u64 %0, t; }" : "=r"(a) : "l"(p));
    return a;
}
__device__ __forceinline__ void ldsm_x4(uint32_t* r, uint32_t addr) {
    asm volatile("ldmatrix.sync.aligned.m8n8.x4.shared.b16 {%0,%1,%2,%3}, [%4];"
                 : "=r"(r[0]), "=r"(r[1]), "=r"(r[2]), "=r"(r[3]) : "r"(addr));
}
__device__ __forceinline__ void mma_bf16(float* d, const uint32_t* a, const uint32_t* b) {
    asm volatile(
        "mma.sync.aligned.m16n8k16.row.col.f32.bf16.bf16.f32 "
        "{%0,%1,%2,%3}, {%4,%5,%6,%7}, {%8,%9}, {%0,%1,%2,%3};"
        : "+f"(d[0]), "+f"(d[1]), "+f"(d[2]), "+f"(d[3])
        : "r"(a[0]), "r"(a[1]), "r"(a[2]), "r"(a[3]), "r"(b[0]), "r"(b[1]));
}
__device__ __forceinline__ uint32_t packbf(__nv_bfloat16 a, __nv_bfloat16 b) {
    uint16_t ua = *(uint16_t*)&a, ub = *(uint16_t*)&b;
    return (uint32_t)ua | ((uint32_t)ub << 16);
}
__device__ __forceinline__ uint32_t pk_bf2(float lo, float hi) {
    uint32_t r; asm("cvt.rn.bf16x2.f32 %0, %1, %2;" : "=r"(r) : "f"(hi), "f"(lo)); return r;
}
__device__ __forceinline__ void cp16(uint32_t saddr, const void* gaddr) {
    asm volatile("cp.async.ca.shared.global [%0], [%1], 16;" :: "r"(saddr), "l"(gaddr) : "memory");
}
#define CP_COMMIT() asm volatile("cp.async.commit_group;" ::: "memory")
#define CP_WAIT1()  asm volatile("cp.async.wait_group 1;" ::: "memory")
#define CP_WAIT0()  asm volatile("cp.async.wait_group 0;" ::: "memory")

// ---------------------------------------------------------------------------
// Kernel 0: weight prep
// ---------------------------------------------------------------------------
__global__ void prep_w_kernel(const float* __restrict__ w_q, const float* __restrict__ w_k,
                              const float* __restrict__ w_v)
{
    int idx = blockIdx.x * blockDim.x + threadIdx.x;
    if (idx >= 192 * E_DIM) return;
    int n = idx / E_DIM, k = idx % E_DIM;
    const float* w = (n < 64) ? w_q : (n < 128) ? w_k : w_v;
    float v = w[k * H_DIM + (n & 63)];
    __nv_bfloat16 hi = __float2bfloat16(v);
    __nv_bfloat16 lo = __float2bfloat16(v - __bfloat162float(hi));
    g_wcat_hi[idx] = hi;
    g_wcat_lo[idx] = lo;
}

// ---------------------------------------------------------------------------
// Kernel 1: split-bf16 mma.sync QKV GEMM + LayerNorm, double-buffered pipeline
// grid = 577 (M tiles of 64), 256 threads, warp tile 32x48
// B streams via cp.async (pre-split bf16); A via reg prefetch + cvt
// ---------------------------------------------------------------------------
#define GK 64
#define NCHUNK (E_DIM / GK)
#define AS 144
#define A_LO_OFF 9216                   // 64*144
#define ABUF(i) ((i) * 18432)           // 2x (hi+lo) A buffers
#define B_LO_OFF 27648                  // 192*144
#define BBUF(i) (36864 + (i) * 55296)   // 2x (hi+lo) B buffers
#define SM_TOTAL (36864 + 2 * 55296)    // 147456
#define STG_S 201

__device__ __forceinline__ void qkv_store_A(char* smc, int tid, const float4* av, uint32_t abuf)
{
#pragma unroll
    for (int it = 0; it < 4; it++) {
        int i = tid + it * 256;
        int r = i >> 4, col = (i & 15) * 4;
        float4 v = av[it];
        __nv_bfloat16 h0 = __float2bfloat16(v.x), h1 = __float2bfloat16(v.y);
        __nv_bfloat16 h2 = __float2bfloat16(v.z), h3 = __float2bfloat16(v.w);
        __nv_bfloat16 l0 = __float2bfloat16(v.x - __bfloat162float(h0));
        __nv_bfloat16 l1 = __float2bfloat16(v.y - __bfloat162float(h1));
        __nv_bfloat16 l2 = __float2bfloat16(v.z - __bfloat162float(h2));
        __nv_bfloat16 l3 = __float2bfloat16(v.w - __bfloat162float(h3));
        uint32_t off = abuf + (uint32_t)(r * AS + col * 2);
        *(uint2*)(smc + off)            = make_uint2(packbf(h0, h1), packbf(h2, h3));
        *(uint2*)(smc + off + A_LO_OFF) = make_uint2(packbf(l0, l1), packbf(l2, l3));
    }
}
__device__ __forceinline__ void qkv_cp_B(uint32_t sb, int tid, int k0, uint32_t bbuf)
{
#pragma unroll
    for (int it = 0; it < 6; it++) {
        int i = tid + it * 256;          // 0..1535
        int r = i >> 3, seg = i & 7;
        uint32_t soff = sb + bbuf + (uint32_t)(r * AS + seg * 16);
        size_t goff = (size_t)r * E_DIM + k0 + seg * 8;
        cp16(soff,            g_wcat_hi + goff);
        cp16(soff + B_LO_OFF, g_wcat_lo + goff);
    }
}

__global__ __launch_bounds__(256) void qkv_mma_kernel(
    const float* __restrict__ x,
    const float* __restrict__ q_gamma, const float* __restrict__ q_beta,
    const float* __restrict__ k_gamma, const float* __restrict__ k_beta)
{
    extern __shared__ char smc[];
    const uint32_t sb = smem_u32(smc);
    const int tid  = threadIdx.x;
    const int wid  = tid >> 5;
    const int lane = tid & 31;
    const int wm   = wid >> 2;
    const int wn   = wid & 3;
    const int m0   = blockIdx.x * 64;

    const uint32_t aOff = (uint32_t)((wm * 32 + (lane & 15)) * AS + (lane >> 4) * 16);
    const uint32_t bOff = (uint32_t)((wn * 48 + ((lane >> 4) << 3) + (lane & 7)) * AS
                                     + ((lane >> 3) & 1) * 16);

    float acc[2][6][4];
#pragma unroll
    for (int i = 0; i < 2; i++)
#pragma unroll
        for (int j = 0; j < 6; j++)
#pragma unroll
            for (int c = 0; c < 4; c++) acc[i][j][c] = 0.f;

    // ---- prologue: chunk 0 + chunk 1 in flight ----
    float4 av[4];
    qkv_cp_B(sb, tid, 0, BBUF(0));
    CP_COMMIT();                                   // group: B(0)
#pragma unroll
    for (int it = 0; it < 4; it++) {
        int i = tid + it * 256;
        int r = i >> 4, col = (i & 15) * 4;
        av[it] = *(const float4*)&x[(size_t)(m0 + r) * E_DIM + 0 + col];
    }
    qkv_store_A(smc, tid, av, ABUF(0));
    qkv_cp_B(sb, tid, GK, BBUF(1));
    CP_COMMIT();                                   // group: B(1)
#pragma unroll
    for (int it = 0; it < 4; it++) {
        int i = tid + it * 256;
        int r = i >> 4, col = (i & 15) * 4;
        av[it] = *(const float4*)&x[(size_t)(m0 + r) * E_DIM + GK + col];
    }

    for (int ch = 0; ch < NCHUNK; ch++) {
        const int cur = ch & 1;
        if (ch < NCHUNK - 1) CP_WAIT1(); else CP_WAIT0();
        __syncthreads();   // B(cur) complete everywhere; A(cur) stores visible

        // ---- MMA on cur buffers ----
        const uint32_t aHi = sb + ABUF(cur) + aOff;
        const uint32_t bHi = sb + BBUF(cur) + bOff;
#pragma unroll
        for (int ks = 0; ks < 4; ks++) {
            const uint32_t kb = (uint32_t)(ks * 32);
            uint32_t ahi[2][4], alo[2][4];
#pragma unroll
            for (int im = 0; im < 2; im++) {
                ldsm_x4(ahi[im], aHi + im * 16 * AS + kb);
                ldsm_x4(alo[im], aHi + A_LO_OFF + im * 16 * AS + kb);
            }
            uint32_t bhi[6][2], blo[6][2];
#pragma unroll
            for (int j = 0; j < 3; j++) {
                uint32_t t[4];
                ldsm_x4(t, bHi + j * 16 * AS + kb);
                bhi[2 * j][0] = t[0]; bhi[2 * j][1] = t[1];
                bhi[2 * j + 1][0] = t[2]; bhi[2 * j + 1][1] = t[3];
                ldsm_x4(t, bHi + B_LO_OFF + j * 16 * AS + kb);
                blo[2 * j][0] = t[0]; blo[2 * j][1] = t[1];
                blo[2 * j + 1][0] = t[2]; blo[2 * j + 1][1] = t[3];
            }
#pragma unroll
            for (int im = 0; im < 2; im++)
#pragma unroll
                for (int jn = 0; jn < 6; jn++) {
                    mma_bf16(acc[im][jn], ahi[im], bhi[jn]);
                    mma_bf16(acc[im][jn], ahi[im], blo[jn]);
                    mma_bf16(acc[im][jn], alo[im], bhi[jn]);
                }
        }

        // stage prefetched A regs into the next buffer
        if (ch < NCHUNK - 1)
            qkv_store_A(smc, tid, av, ABUF((ch + 1) & 1));
        __syncthreads();   // everyone done reading cur before it is overwritten

        // issue loads for chunk ch+2 into the buffer just vacated
        if (ch < NCHUNK - 2) {
            const int k0n = (ch + 2) * GK;
            qkv_cp_B(sb, tid, k0n, BBUF(cur));
            CP_COMMIT();
#pragma unroll
            for (int it = 0; it < 4; it++) {
                int i = tid + it * 256;
                int r = i >> 4, col = (i & 15) * 4;
                av[it] = *(const float4*)&x[(size_t)(m0 + r) * E_DIM + k0n + col];
            }
        }
    }
    __syncthreads();

    float* stage = (float*)smc;
#pragma unroll
    for (int im = 0; im < 2; im++)
#pragma unroll
        for (int jn = 0; jn < 6; jn++) {
            int row = wm * 32 + im * 16 + (lane >> 2);
            int col = wn * 48 + jn * 8 + (lane & 3) * 2;
            stage[row * STG_S + col]           = acc[im][jn][0];
            stage[row * STG_S + col + 1]       = acc[im][jn][1];
            stage[(row + 8) * STG_S + col]     = acc[im][jn][2];
            stage[(row + 8) * STG_S + col + 1] = acc[im][jn][3];
        }
    __syncthreads();

    if (tid < 192) {
        int row = tid & 63;
        int seg = tid >> 6;
        float f[64];
#pragma unroll
        for (int c = 0; c < 64; c++) f[c] = stage[row * STG_S + seg * 64 + c];
        if (seg < 2) {
            const float* gamma = (seg == 0) ? q_gamma : k_gamma;
            const float* beta  = (seg == 0) ? q_beta  : k_beta;
            float s = 0.f;
#pragma unroll
            for (int c = 0; c < 64; c++) s += f[c];
            float mu = s * (1.f / 64.f);
            float v2 = 0.f;
#pragma unroll
            for (int c = 0; c < 64; c++) { float d = f[c] - mu; v2 += d * d; }
            float rstd = rsqrtf(v2 * (1.f / 64.f) + 1e-5f);
#pragma unroll
            for (int c = 0; c < 64; c++) f[c] = (f[c] - mu) * rstd * gamma[c] + beta[c];
        }
        float* outg = (seg == 0) ? g_q : (seg == 1) ? g_k : g_v;
        size_t dst = (size_t)(m0 + row) * H_DIM;
#pragma unroll
        for (int c4 = 0; c4 < 16; c4++)
            *(float4*)&outg[dst + c4 * 4] =
                make_float4(f[c4 * 4], f[c4 * 4 + 1], f[c4 * 4 + 2], f[c4 * 4 + 3]);
    }
}

// ---------------------------------------------------------------------------
// Kernel 2 (v7, unchanged from R10): mma.sync flash attention + Gaussian aug
// ---------------------------------------------------------------------------
#define KT 64
#define NKT 10
#define A_QHI 0
#define A_QLO (A_QHI + 128 * AS)
#define A_KHI (A_QLO + 128 * AS)
#define A_KLO (A_KHI + 64 * AS)
#define A_VHI (A_KLO + 64 * AS)
#define A_VLO (A_VHI + 64 * AS)
#define A_PRM (A_VLO + 64 * AS)
#define A_TOTAL (A_PRM + (5 * 128 + 3 * KT) * 4)

__global__ __launch_bounds__(256) void attn_mma_kernel(
    const float* __restrict__ w_sigma, const float* __restrict__ b_sigma,
    const float* __restrict__ w_alpha, const float* __restrict__ b_alpha,
    float* __restrict__ out)
{
    extern __shared__ char smc[];
    const uint32_t sb = smem_u32(smc);
    float* al_s = (float*)(smc + A_PRM);
    float* ix_s = al_s + 128;
    float* iy_s = ix_s + 128;
    float* gx_s = iy_s + 128;
    float* gy_s = gx_s + 128;
    float* kx_s = gy_s + 128;
    float* ky_s = kx_s + KT;
    float* km_s = ky_s + KT;

    const int tid  = threadIdx.x;
    const int lane = tid & 31;
    const int wid  = tid >> 5;
    const int b    = blockIdx.y;
    const int q0   = blockIdx.x * 128;
    const size_t base = (size_t)b * T_LEN * H_DIM;

#pragma unroll
    for (int it = 0; it < 8; it++) {
        int i = tid + it * 256;
        int r = i >> 4, c4 = i & 15;
        int qi = q0 + r;
        float4 v = make_float4(0.f, 0.f, 0.f, 0.f);
        if (qi < T_LEN) v = *(const float4*)&g_q[base + (size_t)qi * H_DIM + c4 * 4];
        v.x *= 0.125f; v.y *= 0.125f; v.z *= 0.125f; v.w *= 0.125f;
        __nv_bfloat16 h0 = __float2bfloat16(v.x), h1 = __float2bfloat16(v.y);
        __nv_bfloat16 h2 = __float2bfloat16(v.z), h3 = __float2bfloat16(v.w);
        __nv_bfloat16 l0 = __float2bfloat16(v.x - __bfloat162float(h0));
        __nv_bfloat16 l1 = __float2bfloat16(v.y - __bfloat162float(h1));
        __nv_bfloat16 l2 = __float2bfloat16(v.z - __bfloat162float(h2));
        __nv_bfloat16 l3 = __float2bfloat16(v.w - __bfloat162float(h3));
        uint32_t off = (uint32_t)(r * AS + c4 * 8);
        *(uint2*)(smc + A_QHI + off) = make_uint2(packbf(h0, h1), packbf(h2, h3));
        *(uint2*)(smc + A_QLO + off) = make_uint2(packbf(l0, l1), packbf(l2, l3));
    }

    if (tid < 128) {
        int r = tid;
        int qi = q0 + r;
        if (qi >= 1 && qi < T_LEN) {
            const float* qrow = &g_q[base + (size_t)qi * H_DIM];
            float a = 0.f, s0 = 0.f, s1 = 0.f;
#pragma unroll 8
            for (int c = 0; c < 64; c++) {
                float qv = qrow[c];
                a  += qv * w_alpha[c];
                s0 += qv * w_sigma[c * 2 + 0];
                s1 += qv * w_sigma[c * 2 + 1];
            }
            a += b_alpha[0]; s0 += b_sigma[0]; s1 += b_sigma[1];
            float alpha = fmaxf(a, 0.f) + log1pf(expf(-fabsf(a)));
            float sx = 1.f / (1.f + expf(-s0));
            float sy = 1.f / (1.f + expf(-s1));
            al_s[r] = alpha * 0.125f;
            ix_s[r] = 0.5f / (sx * sx);
            iy_s[r] = 0.5f / (sy * sy);
            int gq = qi - 1;
            gx_s[r] = (float)(gq % GW);
            gy_s[r] = (float)(gq / GW);
        } else {
            al_s[r] = 0.f; ix_s[r] = 0.f; iy_s[r] = 0.f;
            gx_s[r] = 0.f; gy_s[r] = 0.f;
        }
    }
    __syncthreads();

    uint32_t qh[4][4], ql[4][4];
    {
        uint32_t aOff = (uint32_t)((wid * 16 + (lane & 15)) * AS + (lane >> 4) * 16);
#pragma unroll
        for (int c = 0; c < 4; c++) {
            ldsm_x4(qh[c], sb + A_QHI + aOff + c * 32);
            ldsm_x4(ql[c], sb + A_QLO + aOff + c * 32);
        }
    }

    const int r1  = lane >> 2;
    const int lr1 = wid * 16 + r1;
    const float al1 = al_s[lr1],     ix1 = ix_s[lr1],     iy1 = iy_s[lr1];
    const float gx1 = gx_s[lr1],     gy1 = gy_s[lr1];
    const float al2 = al_s[lr1 + 8], ix2 = ix_s[lr1 + 8], iy2 = iy_s[lr1 + 8];
    const float gx2 = gx_s[lr1 + 8], gy2 = gy_s[lr1 + 8];

    float m1 = -1e30f, m2 = -1e30f, l1 = 0.f, l2 = 0.f;
    float oacc[8][4];
#pragma unroll
    for (int n = 0; n < 8; n++)
#pragma unroll
        for (int c = 0; c < 4; c++) oacc[n][c] = 0.f;

    for (int kt = 0; kt < NKT; kt++) {
        const int k0 = kt * KT;
        __syncthreads();

#pragma unroll
        for (int it = 0; it < 4; it++) {
            int i = tid + it * 256;
            int r = i >> 4, c4 = i & 15;
            int ki = k0 + r;
            float4 v = make_float4(0.f, 0.f, 0.f, 0.f);
            if (ki < T_LEN) v = *(const float4*)&g_k[base + (size_t)ki * H_DIM + c4 * 4];
            __nv_bfloat16 h0 = __float2bfloat16(v.x), h1 = __float2bfloat16(v.y);
            __nv_bfloat16 h2 = __float2bfloat16(v.z), h3 = __float2bfloat16(v.w);
            __nv_bfloat16 l0 = __float2bfloat16(v.x - __bfloat162float(h0));
            __nv_bfloat16 l1b = __float2bfloat16(v.y - __bfloat162float(h1));
            __nv_bfloat16 l2 = __float2bfloat16(v.z - __bfloat162float(h2));
            __nv_bfloat16 l3 = __float2bfloat16(v.w - __bfloat162float(h3));
            uint32_t off = (uint32_t)(r * AS + c4 * 8);
            *(uint2*)(smc + A_KHI + off) = make_uint2(packbf(h0, h1), packbf(h2, h3));
            *(uint2*)(smc + A_KLO + off) = make_uint2(packbf(l0, l1b), packbf(l2, l3));
        }
#pragma unroll
        for (int it = 0; it < 2; it++) {
            int s = tid + it * 256;
            int kp = s & 31, h4 = s >> 5;
            int ki0 = k0 + 2 * kp;
            float4 va = make_float4(0.f, 0.f, 0.f, 0.f), vb = va;
            if (ki0 < T_LEN)     va = *(const float4*)&g_v[base + (size_t)ki0 * H_DIM + h4 * 4];
            if (ki0 + 1 < T_LEN) vb = *(const float4*)&g_v[base + (size_t)(ki0 + 1) * H_DIM + h4 * 4];
            float a4[4] = {va.x, va.y, va.z, va.w};
            float b4[4] = {vb.x, vb.y, vb.z, vb.w};
#pragma unroll
            for (int j = 0; j < 4; j++) {
                int h = h4 * 4 + j;
                __nv_bfloat16 h0 = __float2bfloat16(a4[j]);
                __nv_bfloat16 h1 = __float2bfloat16(b4[j]);
                __nv_bfloat16 l0 = __float2bfloat16(a4[j] - __bfloat162float(h0));
                __nv_bfloat16 l1b = __float2bfloat16(b4[j] - __bfloat162float(h1));
                uint32_t off = (uint32_t)(h * AS + kp * 4);
                *(uint32_t*)(smc + A_VHI + off) = packbf(h0, h1);
                *(uint32_t*)(smc + A_VLO + off) = packbf(l0, l1b);
            }
        }
        if (tid < KT) {
            int ki = k0 + tid;
            bool kvalid = ki < T_LEN;
            bool kaug = (ki >= 1) && kvalid;
            int g = kaug ? ki - 1 : 0;
            kx_s[tid] = kaug ? (float)(g % GW) : -1e9f;
            ky_s[tid] = kaug ? (float)(g / GW) : 0.f;
            km_s[tid] = kvalid ? 0.f : -1e30f;
        }
        __syncthreads();

        float sc[8][4];
#pragma unroll
        for (int n = 0; n < 8; n++)
#pragma unroll
            for (int c = 0; c < 4; c++) sc[n][c] = 0.f;

#pragma unroll
        for (int c = 0; c < 4; c++) {
#pragma unroll
            for (int g = 0; g < 4; g++) {
                uint32_t bOff = (uint32_t)((g * 16 + ((lane >> 4) << 3) + (lane & 7)) * AS
                                           + ((lane >> 3) & 1) * 16 + c * 32);
                uint32_t th[4], tl[4];
                ldsm_x4(th, sb + A_KHI + bOff);
                ldsm_x4(tl, sb + A_KLO + bOff);
                mma_bf16(sc[2 * g],     qh[c], th);
                mma_bf16(sc[2 * g],     qh[c], tl);
                mma_bf16(sc[2 * g],     ql[c], th);
                mma_bf16(sc[2 * g + 1], qh[c], th + 2);
                mma_bf16(sc[2 * g + 1], qh[c], tl + 2);
                mma_bf16(sc[2 * g + 1], ql[c], th + 2);
            }
        }

#pragma unroll
        for (int n = 0; n < 8; n++) {
            int kc0 = n * 8 + (lane & 3) * 2;
            float kxa = kx_s[kc0],     kya = ky_s[kc0],     kma = km_s[kc0];
            float kxb = kx_s[kc0 + 1], kyb = ky_s[kc0 + 1], kmb = km_s[kc0 + 1];
            float dxa1 = gx1 - kxa, dya1 = gy1 - kya;
            float dxb1 = gx1 - kxb, dyb1 = gy1 - kyb;
            float dxa2 = gx2 - kxa, dya2 = gy2 - kya;
            float dxb2 = gx2 - kxb, dyb2 = gy2 - kyb;
            sc[n][0] += al1 * __expf(-dxa1 * dxa1 * ix1 - dya1 * dya1 * iy1) + kma;
            sc[n][1] += al1 * __expf(-dxb1 * dxb1 * ix1 - dyb1 * dyb1 * iy1) + kmb;
            sc[n][2] += al2 * __expf(-dxa2 * dxa2 * ix2 - dya2 * dya2 * iy2) + kma;
            sc[n][3] += al2 * __expf(-dxb2 * dxb2 * ix2 - dyb2 * dyb2 * iy2) + kmb;
        }

        float mx1 = -1e30f, mx2 = -1e30f;
#pragma unroll
        for (int n = 0; n < 8; n++) {
            mx1 = fmaxf(mx1, fmaxf(sc[n][0], sc[n][1]));
            mx2 = fmaxf(mx2, fmaxf(sc[n][2], sc[n][3]));
        }
        mx1 = fmaxf(mx1, __shfl_xor_sync(0xffffffffu, mx1, 1));
        mx1 = fmaxf(mx1, __shfl_xor_sync(0xffffffffu, mx1, 2));
        mx2 = fmaxf(mx2, __shfl_xor_sync(0xffffffffu, mx2, 1));
        mx2 = fmaxf(mx2, __shfl_xor_sync(0xffffffffu, mx2, 2));

        float mnew1 = fmaxf(m1, mx1), mnew2 = fmaxf(m2, mx2);
        float scf1 = __expf(m1 - mnew1), scf2 = __expf(m2 - mnew2);
        m1 = mnew1; m2 = mnew2;

        float sum1 = 0.f, sum2 = 0.f;
#pragma unroll
        for (int n = 0; n < 8; n++) {
            float p0 = __expf(sc[n][0] - m1);
            float p1 = __expf(sc[n][1] - m1);
            float p2 = __expf(sc[n][2] - m2);
            float p3 = __expf(sc[n][3] - m2);
            sc[n][0] = p0; sc[n][1] = p1; sc[n][2] = p2; sc[n][3] = p3;
            sum1 += p0 + p1; sum2 += p2 + p3;
        }
        sum1 += __shfl_xor_sync(0xffffffffu, sum1, 1);
        sum1 += __shfl_xor_sync(0xffffffffu, sum1, 2);
        sum2 += __shfl_xor_sync(0xffffffffu, sum2, 1);
        sum2 += __shfl_xor_sync(0xffffffffu, sum2, 2);
        l1 = l1 * scf1 + sum1;
        l2 = l2 * scf2 + sum2;
#pragma unroll
        for (int n = 0; n < 8; n++) {
            oacc[n][0] *= scf1; oacc[n][1] *= scf1;
            oacc[n][2] *= scf2; oacc[n][3] *= scf2;
        }

#pragma unroll
        for (int c = 0; c < 4; c++) {
            uint32_t ahi[4], alo[4];
#pragma unroll
            for (int t = 0; t < 2; t++) {
                float p0 = sc[2 * c + t][0], p1 = sc[2 * c + t][1];
                float p2 = sc[2 * c + t][2], p3 = sc[2 * c + t][3];
                uint32_t h01 = pk_bf2(p0, p1);
                uint32_t h23 = pk_bf2(p2, p3);
                float r0 = p0 - __uint_as_float(h01 << 16);
                float r1b = p1 - __uint_as_float(h01 & 0xffff0000u);
                float r2 = p2 - __uint_as_float(h23 << 16);
                float r3 = p3 - __uint_as_float(h23 & 0xffff0000u);
                ahi[2 * t]     = h01;
                ahi[2 * t + 1] = h23;
                alo[2 * t]     = pk_bf2(r0, r1b);
                alo[2 * t + 1] = pk_bf2(r2, r3);
            }
            uint32_t af_hi[4] = {ahi[0], ahi[1], ahi[2], ahi[3]};
            uint32_t af_lo[4] = {alo[0], alo[1], alo[2], alo[3]};
#pragma unroll
            for (int g = 0; g < 4; g++) {
                uint32_t bOff = (uint32_t)((g * 16 + ((lane >> 4) << 3) + (lane & 7)) * AS
                                           + ((lane >> 3) & 1) * 16 + c * 32);
                uint32_t th[4], tl[4];
                ldsm_x4(th, sb + A_VHI + bOff);
                ldsm_x4(tl, sb + A_VLO + bOff);
                mma_bf16(oacc[2 * g],     af_hi, th);
                mma_bf16(oacc[2 * g],     af_hi, tl);
                mma_bf16(oacc[2 * g],     af_lo, th);
                mma_bf16(oacc[2 * g + 1], af_hi, th + 2);
                mma_bf16(oacc[2 * g + 1], af_hi, tl + 2);
                mma_bf16(oacc[2 * g + 1], af_lo, th + 2);
            }
        }
    }

    float inv1 = 1.f / l1, inv2 = 1.f / l2;
    int qi1 = q0 + wid * 16 + r1;
    int qi2 = qi1 + 8;
#pragma unroll
    for (int n = 0; n < 8; n++) {
        int h = n * 8 + (lane & 3) * 2;
        if (qi1 < T_LEN) {
            float2 o = make_float2(oacc[n][0] * inv1, oacc[n][1] * inv1);
            *(float2*)&out[base + (size_t)qi1 * H_DIM + h] = o;
        }
        if (qi2 < T_LEN) {
            float2 o = make_float2(oacc[n][2] * inv2, oacc[n][3] * inv2);
            *(float2*)&out[base + (size_t)qi2 * H_DIM + h] = o;
        }
    }
}

// ---------------------------------------------------------------------------
extern "C" void kernel_launch(void* const* d_in, const int* in_sizes, int n_in,
                              void* d_out, int out_size)
{
    const float* x       = (const float*)d_in[0];
    const float* w_q     = (const float*)d_in[1];
    const float* w_k     = (const float*)d_in[2];
    const float* w_v     = (const float*)d_in[3];
    const float* q_gamma = (const float*)d_in[4];
    const float* q_beta  = (const float*)d_in[5];
    const float* k_gamma = (const float*)d_in[6];
    const float* k_beta  = (const float*)d_in[7];
    const float* w_sigma = (const float*)d_in[8];
    const float* b_sigma = (const float*)d_in[9];
    const float* w_alpha = (const float*)d_in[10];
    const float* b_alpha = (const float*)d_in[11];
    float* out = (float*)d_out;

    prep_w_kernel<<<(192 * E_DIM + 255) / 256, 256>>>(w_q, w_k, w_v);

    cudaFuncSetAttribute(qkv_mma_kernel, cudaFuncAttributeMaxDynamicSharedMemorySize, SM_TOTAL);
    qkv_mma_kernel<<<M_ROWS / 64, 256, SM_TOTAL>>>(x, q_gamma, q_beta, k_gamma, k_beta);

    cudaFuncSetAttribute(attn_mma_kernel, cudaFuncAttributeMaxDynamicSharedMemorySize, A_TOTAL);
    dim3 grid2((T_LEN + 127) / 128, B_SZ);
    attn_mma_kernel<<<grid2, 256, A_TOTAL>>>(w_sigma, b_sigma, w_alpha, b_alpha, out);
}

// round 13
// speedup vs baseline: 2.6937x; 1.1831x over previous
#include <cuda_runtime.h>
#include <cuda_bf16.h>
#include <math.h>
#include <stdint.h>

#define M_ROWS 36928   // B*T = 64*577
#define E_DIM  768
#define H_DIM  64
#define T_LEN  577
#define B_SZ   64
#define GW     24
#define TPAD   640     // padded T for transposed V

// scratch (static device arrays; no allocation)
__device__ float g_q[M_ROWS * H_DIM];
// K pre-split bf16, row layout, +64 padded rows (zeroed) for cp.async overrun
__device__ __nv_bfloat16 g_k_hi[(M_ROWS + 64) * H_DIM];
__device__ __nv_bfloat16 g_k_lo[(M_ROWS + 64) * H_DIM];
// V pre-split + pre-transposed: [b][h][t], t padded to TPAD (pad zeroed)
__device__ __nv_bfloat16 g_vT_hi[B_SZ * H_DIM * TPAD];
__device__ __nv_bfloat16 g_vT_lo[B_SZ * H_DIM * TPAD];
// concatenated transposed weights, split bf16: [n=192][k=768]
__device__ __nv_bfloat16 g_wcat_hi[192 * E_DIM];
__device__ __nv_bfloat16 g_wcat_lo[192 * E_DIM];

__device__ __forceinline__ uint32_t smem_u32(const void* p) {
    uint32_t a;
    asm("{ .reg .u64 t; cvta.to.shared.u64 t, %1; cvt.u32.u64 %0, t; }" : "=r"(a) : "l"(p));
    return a;
}
__device__ __forceinline__ void ldsm_x4(uint32_t* r, uint32_t addr) {
    asm volatile("ldmatrix.sync.aligned.m8n8.x4.shared.b16 {%0,%1,%2,%3}, [%4];"
                 : "=r"(r[0]), "=r"(r[1]), "=r"(r[2]), "=r"(r[3]) : "r"(addr));
}
__device__ __forceinline__ void mma_bf16(float* d, const uint32_t* a, const uint32_t* b) {
    asm volatile(
        "mma.sync.aligned.m16n8k16.row.col.f32.bf16.bf16.f32 "
        "{%0,%1,%2,%3}, {%4,%5,%6,%7}, {%8,%9}, {%0,%1,%2,%3};"
        : "+f"(d[0]), "+f"(d[1]), "+f"(d[2]), "+f"(d[3])
        : "r"(a[0]), "r"(a[1]), "r"(a[2]), "r"(a[3]), "r"(b[0]), "r"(b[1]));
}
__device__ __forceinline__ uint32_t packbf(__nv_bfloat16 a, __nv_bfloat16 b) {
    uint16_t ua = *(uint16_t*)&a, ub = *(uint16_t*)&b;
    return (uint32_t)ua | ((uint32_t)ub << 16);
}
__device__ __forceinline__ uint32_t pk_bf2(float lo, float hi) {
    uint32_t r; asm("cvt.rn.bf16x2.f32 %0, %1, %2;" : "=r"(r) : "f"(hi), "f"(lo)); return r;
}
__device__ __forceinline__ void cp16(uint32_t saddr, const void* gaddr) {
    asm volatile("cp.async.ca.shared.global [%0], [%1], 16;" :: "r"(saddr), "l"(gaddr) : "memory");
}
#define CP_COMMIT() asm volatile("cp.async.commit_group;" ::: "memory")
#define CP_WAIT1()  asm volatile("cp.async.wait_group 1;" ::: "memory")
#define CP_WAIT0()  asm volatile("cp.async.wait_group 0;" ::: "memory")

// ---------------------------------------------------------------------------
// Kernel 0a: weight prep
// ---------------------------------------------------------------------------
__global__ void prep_w_kernel(const float* __restrict__ w_q, const float* __restrict__ w_k,
                              const float* __restrict__ w_v)
{
    int idx = blockIdx.x * blockDim.x + threadIdx.x;
    if (idx >= 192 * E_DIM) return;
    int n = idx / E_DIM, k = idx % E_DIM;
    const float* w = (n < 64) ? w_q : (n < 128) ? w_k : w_v;
    float v = w[k * H_DIM + (n & 63)];
    __nv_bfloat16 hi = __float2bfloat16(v);
    __nv_bfloat16 lo = __float2bfloat16(v - __bfloat162float(hi));
    g_wcat_hi[idx] = hi;
    g_wcat_lo[idx] = lo;
}

// ---------------------------------------------------------------------------
// Kernel 0b: zero the padding regions (K pad rows; vT t-pad) for NaN safety
// ---------------------------------------------------------------------------
__global__ void pad_kernel()
{
    int idx = blockIdx.x * blockDim.x + threadIdx.x;
    const __nv_bfloat16 z = __float2bfloat16(0.f);
    if (idx < 64 * H_DIM) {
        g_k_hi[(size_t)M_ROWS * H_DIM + idx] = z;
        g_k_lo[(size_t)M_ROWS * H_DIM + idx] = z;
    }
    const int NPAD = TPAD - T_LEN;                 // 63
    const int NV = B_SZ * H_DIM * NPAD;            // 258048
    if (idx < NV) {
        int b = idx / (H_DIM * NPAD);
        int rem = idx % (H_DIM * NPAD);
        int h = rem / NPAD;
        int j = rem % NPAD;
        size_t pos = ((size_t)(b * H_DIM + h)) * TPAD + T_LEN + j;
        g_vT_hi[pos] = z;
        g_vT_lo[pos] = z;
    }
}

// ---------------------------------------------------------------------------
// Kernel 1: split-bf16 mma.sync QKV GEMM + LayerNorm, double-buffered pipeline
// Epilogue emits attention-ready operands: q fp32; k split bf16 rows;
// v split bf16 TRANSPOSED per batch.
// ---------------------------------------------------------------------------
#define GK 64
#define NCHUNK (E_DIM / GK)
#define AS 144
#define A_LO_OFF 9216
#define ABUF(i) ((i) * 18432)
#define B_LO_OFF 27648
#define BBUF(i) (36864 + (i) * 55296)
#define SM_TOTAL (36864 + 2 * 55296)
#define STG_S 201

__device__ __forceinline__ void qkv_store_A(char* smc, int tid, const float4* av, uint32_t abuf)
{
#pragma unroll
    for (int it = 0; it < 4; it++) {
        int i = tid + it * 256;
        int r = i >> 4, col = (i & 15) * 4;
        float4 v = av[it];
        __nv_bfloat16 h0 = __float2bfloat16(v.x), h1 = __float2bfloat16(v.y);
        __nv_bfloat16 h2 = __float2bfloat16(v.z), h3 = __float2bfloat16(v.w);
        __nv_bfloat16 l0 = __float2bfloat16(v.x - __bfloat162float(h0));
        __nv_bfloat16 l1 = __float2bfloat16(v.y - __bfloat162float(h1));
        __nv_bfloat16 l2 = __float2bfloat16(v.z - __bfloat162float(h2));
        __nv_bfloat16 l3 = __float2bfloat16(v.w - __bfloat162float(h3));
        uint32_t off = abuf + (uint32_t)(r * AS + col * 2);
        *(uint2*)(smc + off)            = make_uint2(packbf(h0, h1), packbf(h2, h3));
        *(uint2*)(smc + off + A_LO_OFF) = make_uint2(packbf(l0, l1), packbf(l2, l3));
    }
}
__device__ __forceinline__ void qkv_cp_B(uint32_t sb, int tid, int k0, uint32_t bbuf)
{
#pragma unroll
    for (int it = 0; it < 6; it++) {
        int i = tid + it * 256;
        int r = i >> 3, seg = i & 7;
        uint32_t soff = sb + bbuf + (uint32_t)(r * AS + seg * 16);
        size_t goff = (size_t)r * E_DIM + k0 + seg * 8;
        cp16(soff,            g_wcat_hi + goff);
        cp16(soff + B_LO_OFF, g_wcat_lo + goff);
    }
}

__global__ __launch_bounds__(256) void qkv_mma_kernel(
    const float* __restrict__ x,
    const float* __restrict__ q_gamma, const float* __restrict__ q_beta,
    const float* __restrict__ k_gamma, const float* __restrict__ k_beta)
{
    extern __shared__ char smc[];
    const uint32_t sb = smem_u32(smc);
    const int tid  = threadIdx.x;
    const int wid  = tid >> 5;
    const int lane = tid & 31;
    const int wm   = wid >> 2;
    const int wn   = wid & 3;
    const int m0   = blockIdx.x * 64;

    const uint32_t aOff = (uint32_t)((wm * 32 + (lane & 15)) * AS + (lane >> 4) * 16);
    const uint32_t bOff = (uint32_t)((wn * 48 + ((lane >> 4) << 3) + (lane & 7)) * AS
                                     + ((lane >> 3) & 1) * 16);

    float acc[2][6][4];
#pragma unroll
    for (int i = 0; i < 2; i++)
#pragma unroll
        for (int j = 0; j < 6; j++)
#pragma unroll
            for (int c = 0; c < 4; c++) acc[i][j][c] = 0.f;

    float4 av[4];
    qkv_cp_B(sb, tid, 0, BBUF(0));
    CP_COMMIT();
#pragma unroll
    for (int it = 0; it < 4; it++) {
        int i = tid + it * 256;
        int r = i >> 4, col = (i & 15) * 4;
        av[it] = *(const float4*)&x[(size_t)(m0 + r) * E_DIM + 0 + col];
    }
    qkv_store_A(smc, tid, av, ABUF(0));
    qkv_cp_B(sb, tid, GK, BBUF(1));
    CP_COMMIT();
#pragma unroll
    for (int it = 0; it < 4; it++) {
        int i = tid + it * 256;
        int r = i >> 4, col = (i & 15) * 4;
        av[it] = *(const float4*)&x[(size_t)(m0 + r) * E_DIM + GK + col];
    }

    for (int ch = 0; ch < NCHUNK; ch++) {
        const int cur = ch & 1;
        if (ch < NCHUNK - 1) CP_WAIT1(); else CP_WAIT0();
        __syncthreads();

        const uint32_t aHi = sb + ABUF(cur) + aOff;
        const uint32_t bHi = sb + BBUF(cur) + bOff;
#pragma unroll
        for (int ks = 0; ks < 4; ks++) {
            const uint32_t kb = (uint32_t)(ks * 32);
            uint32_t ahi[2][4], alo[2][4];
#pragma unroll
            for (int im = 0; im < 2; im++) {
                ldsm_x4(ahi[im], aHi + im * 16 * AS + kb);
                ldsm_x4(alo[im], aHi + A_LO_OFF + im * 16 * AS + kb);
            }
            uint32_t bhi[6][2], blo[6][2];
#pragma unroll
            for (int j = 0; j < 3; j++) {
                uint32_t t[4];
                ldsm_x4(t, bHi + j * 16 * AS + kb);
                bhi[2 * j][0] = t[0]; bhi[2 * j][1] = t[1];
                bhi[2 * j + 1][0] = t[2]; bhi[2 * j + 1][1] = t[3];
                ldsm_x4(t, bHi + B_LO_OFF + j * 16 * AS + kb);
                blo[2 * j][0] = t[0]; blo[2 * j][1] = t[1];
                blo[2 * j + 1][0] = t[2]; blo[2 * j + 1][1] = t[3];
            }
#pragma unroll
            for (int im = 0; im < 2; im++)
#pragma unroll
                for (int jn = 0; jn < 6; jn++) {
                    mma_bf16(acc[im][jn], ahi[im], bhi[jn]);
                    mma_bf16(acc[im][jn], ahi[im], blo[jn]);
                    mma_bf16(acc[im][jn], alo[im], bhi[jn]);
                }
        }

        if (ch < NCHUNK - 1)
            qkv_store_A(smc, tid, av, ABUF((ch + 1) & 1));
        __syncthreads();

        if (ch < NCHUNK - 2) {
            const int k0n = (ch + 2) * GK;
            qkv_cp_B(sb, tid, k0n, BBUF(cur));
            CP_COMMIT();
#pragma unroll
            for (int it = 0; it < 4; it++) {
                int i = tid + it * 256;
                int r = i >> 4, col = (i & 15) * 4;
                av[it] = *(const float4*)&x[(size_t)(m0 + r) * E_DIM + k0n + col];
            }
        }
    }
    __syncthreads();

    float* stage = (float*)smc;
#pragma unroll
    for (int im = 0; im < 2; im++)
#pragma unroll
        for (int jn = 0; jn < 6; jn++) {
            int row = wm * 32 + im * 16 + (lane >> 2);
            int col = wn * 48 + jn * 8 + (lane & 3) * 2;
            stage[row * STG_S + col]           = acc[im][jn][0];
            stage[row * STG_S + col + 1]       = acc[im][jn][1];
            stage[(row + 8) * STG_S + col]     = acc[im][jn][2];
            stage[(row + 8) * STG_S + col + 1] = acc[im][jn][3];
        }
    __syncthreads();

    if (tid < 192) {
        int row = tid & 63;
        int seg = tid >> 6;
        int m = m0 + row;
        float f[64];
#pragma unroll
        for (int c = 0; c < 64; c++) f[c] = stage[row * STG_S + seg * 64 + c];
        if (seg < 2) {
            const float* gamma = (seg == 0) ? q_gamma : k_gamma;
            const float* beta  = (seg == 0) ? q_beta  : k_beta;
            float s = 0.f;
#pragma unroll
            for (int c = 0; c < 64; c++) s += f[c];
            float mu = s * (1.f / 64.f);
            float v2 = 0.f;
#pragma unroll
            for (int c = 0; c < 64; c++) { float d = f[c] - mu; v2 += d * d; }
            float rstd = rsqrtf(v2 * (1.f / 64.f) + 1e-5f);
#pragma unroll
            for (int c = 0; c < 64; c++) f[c] = (f[c] - mu) * rstd * gamma[c] + beta[c];
        }
        if (seg == 0) {
            size_t dst = (size_t)m * H_DIM;
#pragma unroll
            for (int c4 = 0; c4 < 16; c4++)
                *(float4*)&g_q[dst + c4 * 4] =
                    make_float4(f[c4 * 4], f[c4 * 4 + 1], f[c4 * 4 + 2], f[c4 * 4 + 3]);
        } else if (seg == 1) {
            uint32_t hp[32], lp[32];
#pragma unroll
            for (int c2 = 0; c2 < 32; c2++) {
                __nv_bfloat16 h0 = __float2bfloat16(f[2 * c2]);
                __nv_bfloat16 h1 = __float2bfloat16(f[2 * c2 + 1]);
                __nv_bfloat16 l0 = __float2bfloat16(f[2 * c2] - __bfloat162float(h0));
                __nv_bfloat16 l1 = __float2bfloat16(f[2 * c2 + 1] - __bfloat162float(h1));
                hp[c2] = packbf(h0, h1);
                lp[c2] = packbf(l0, l1);
            }
            uint4* dh = (uint4*)(g_k_hi + (size_t)m * H_DIM);
            uint4* dl = (uint4*)(g_k_lo + (size_t)m * H_DIM);
#pragma unroll
            for (int c = 0; c < 8; c++) {
                dh[c] = *(uint4*)&hp[c * 4];
                dl[c] = *(uint4*)&lp[c * 4];
            }
        } else {
            int bb = m / T_LEN;
            int t  = m - bb * T_LEN;
            __nv_bfloat16* dh = g_vT_hi + ((size_t)bb * H_DIM) * TPAD + t;
            __nv_bfloat16* dl = g_vT_lo + ((size_t)bb * H_DIM) * TPAD + t;
#pragma unroll
            for (int h = 0; h < 64; h++) {
                __nv_bfloat16 hi = __float2bfloat16(f[h]);
                __nv_bfloat16 lo = __float2bfloat16(f[h] - __bfloat162float(hi));
                dh[(size_t)h * TPAD] = hi;
                dl[(size_t)h * TPAD] = lo;
            }
        }
    }
}

// ---------------------------------------------------------------------------
// Kernel 2 (v8): mma.sync flash attention, double-buffered cp.async K/V
// Pre-split K rows + pre-transposed V stream directly into the verified
// smem layouts; per-tile cvt work eliminated; grid tables precomputed.
// ---------------------------------------------------------------------------
#define KT 64
#define NKT 10
#define AQ_HI 0
#define AQ_LO 18432
#define KB(i)  (36864 + (i) * 36864)
#define KB_KLO 9216
#define KB_VHI 18432
#define KB_VLO 27648
#define AP_OFF 110592
// params: al,ix,iy,gx,gy (5*128 fl) then kxA,kyA,kmA (3*640 fl)
#define A_TOTAL (AP_OFF + (5 * 128 + 3 * TPAD) * 4)

__device__ __forceinline__ void attn_cp_tile(uint32_t sb, int tid, int krow0, int vbase, int k0,
                                             uint32_t buf)
{
    // K tile: 64 rows x 128B, hi+lo
#pragma unroll
    for (int it = 0; it < 2; it++) {
        int i = tid + it * 256;          // 0..511
        int r = i >> 3, seg = i & 7;
        uint32_t soff = sb + buf + (uint32_t)(r * AS + seg * 16);
        size_t g = ((size_t)(krow0 + r)) * H_DIM + seg * 8;
        cp16(soff,          g_k_hi + g);
        cp16(soff + KB_KLO, g_k_lo + g);
    }
    // V tile: 64 h-rows x 128B (k slice), hi+lo
#pragma unroll
    for (int it = 0; it < 2; it++) {
        int i = tid + it * 256;
        int h = i >> 3, seg = i & 7;
        uint32_t soff = sb + buf + KB_VHI + (uint32_t)(h * AS + seg * 16);
        size_t g = ((size_t)(vbase + h)) * TPAD + k0 + seg * 8;
        cp16(soff,                       g_vT_hi + g);
        cp16(soff + (KB_VLO - KB_VHI),   g_vT_lo + g);
    }
}

__global__ __launch_bounds__(256) void attn_mma_kernel(
    const float* __restrict__ w_sigma, const float* __restrict__ b_sigma,
    const float* __restrict__ w_alpha, const float* __restrict__ b_alpha,
    float* __restrict__ out)
{
    extern __shared__ char smc[];
    const uint32_t sb = smem_u32(smc);
    float* al_s = (float*)(smc + AP_OFF);
    float* ix_s = al_s + 128;
    float* iy_s = ix_s + 128;
    float* gx_s = iy_s + 128;
    float* gy_s = gx_s + 128;
    float* kxA  = gy_s + 128;      // [TPAD]
    float* kyA  = kxA + TPAD;
    float* kmA  = kyA + TPAD;

    const int tid  = threadIdx.x;
    const int lane = tid & 31;
    const int wid  = tid >> 5;
    const int b    = blockIdx.y;
    const int q0   = blockIdx.x * 128;
    const size_t base = (size_t)b * T_LEN * H_DIM;
    const int krow0 = b * T_LEN;
    const int vbase = b * H_DIM;

    // start streaming tiles 0 and 1 immediately
    attn_cp_tile(sb, tid, krow0 + 0,  vbase, 0,  KB(0));
    CP_COMMIT();
    attn_cp_tile(sb, tid, krow0 + KT, vbase, KT, KB(1));
    CP_COMMIT();

    // ---- load Q (fold 0.125), split bf16 hi/lo ----
#pragma unroll
    for (int it = 0; it < 8; it++) {
        int i = tid + it * 256;
        int r = i >> 4, c4 = i & 15;
        int qi = q0 + r;
        float4 v = make_float4(0.f, 0.f, 0.f, 0.f);
        if (qi < T_LEN) v = *(const float4*)&g_q[base + (size_t)qi * H_DIM + c4 * 4];
        v.x *= 0.125f; v.y *= 0.125f; v.z *= 0.125f; v.w *= 0.125f;
        __nv_bfloat16 h0 = __float2bfloat16(v.x), h1 = __float2bfloat16(v.y);
        __nv_bfloat16 h2 = __float2bfloat16(v.z), h3 = __float2bfloat16(v.w);
        __nv_bfloat16 l0 = __float2bfloat16(v.x - __bfloat162float(h0));
        __nv_bfloat16 l1 = __float2bfloat16(v.y - __bfloat162float(h1));
        __nv_bfloat16 l2 = __float2bfloat16(v.z - __bfloat162float(h2));
        __nv_bfloat16 l3 = __float2bfloat16(v.w - __bfloat162float(h3));
        uint32_t off = (uint32_t)(r * AS + c4 * 8);
        *(uint2*)(smc + AQ_HI + off) = make_uint2(packbf(h0, h1), packbf(h2, h3));
        *(uint2*)(smc + AQ_LO + off) = make_uint2(packbf(l0, l1), packbf(l2, l3));
    }

    // ---- per-q-row aug params ----
    if (tid < 128) {
        int r = tid;
        int qi = q0 + r;
        if (qi >= 1 && qi < T_LEN) {
            const float* qrow = &g_q[base + (size_t)qi * H_DIM];
            float a = 0.f, s0 = 0.f, s1 = 0.f;
#pragma unroll 8
            for (int c = 0; c < 64; c++) {
                float qv = qrow[c];
                a  += qv * w_alpha[c];
                s0 += qv * w_sigma[c * 2 + 0];
                s1 += qv * w_sigma[c * 2 + 1];
            }
            a += b_alpha[0]; s0 += b_sigma[0]; s1 += b_sigma[1];
            float alpha = fmaxf(a, 0.f) + log1pf(expf(-fabsf(a)));
            float sx = 1.f / (1.f + expf(-s0));
            float sy = 1.f / (1.f + expf(-s1));
            al_s[r] = alpha * 0.125f;
            ix_s[r] = 0.5f / (sx * sx);
            iy_s[r] = 0.5f / (sy * sy);
            int gq = qi - 1;
            gx_s[r] = (float)(gq % GW);
            gy_s[r] = (float)(gq / GW);
        } else {
            al_s[r] = 0.f; ix_s[r] = 0.f; iy_s[r] = 0.f;
            gx_s[r] = 0.f; gy_s[r] = 0.f;
        }
    }
    // ---- k-column grid tables (once per block) ----
#pragma unroll
    for (int it = 0; it < 3; it++) {
        int ki = tid + it * 256;
        if (ki < TPAD) {
            bool kvalid = ki < T_LEN;
            bool kaug = (ki >= 1) && kvalid;
            int g = kaug ? ki - 1 : 0;
            kxA[ki] = kaug ? (float)(g % GW) : -1e9f;
            kyA[ki] = kaug ? (float)(g / GW) : 0.f;
            kmA[ki] = kvalid ? 0.f : -1e30f;
        }
    }
    __syncthreads();

    // ---- Q fragments resident in registers ----
    uint32_t qh[4][4], ql[4][4];
    {
        uint32_t aOff = (uint32_t)((wid * 16 + (lane & 15)) * AS + (lane >> 4) * 16);
#pragma unroll
        for (int c = 0; c < 4; c++) {
            ldsm_x4(qh[c], sb + AQ_HI + aOff + c * 32);
            ldsm_x4(ql[c], sb + AQ_LO + aOff + c * 32);
        }
    }

    const int r1  = lane >> 2;
    const int lr1 = wid * 16 + r1;
    const float al1 = al_s[lr1],     ix1 = ix_s[lr1],     iy1 = iy_s[lr1];
    const float gx1 = gx_s[lr1],     gy1 = gy_s[lr1];
    const float al2 = al_s[lr1 + 8], ix2 = ix_s[lr1 + 8], iy2 = iy_s[lr1 + 8];
    const float gx2 = gx_s[lr1 + 8], gy2 = gy_s[lr1 + 8];

    float m1 = -1e30f, m2 = -1e30f, l1 = 0.f, l2 = 0.f;
    float oacc[8][4];
#pragma unroll
    for (int n = 0; n < 8; n++)
#pragma unroll
        for (int c = 0; c < 4; c++) oacc[n][c] = 0.f;

    for (int kt = 0; kt < NKT; kt++) {
        const int k0 = kt * KT;
        const int cur = kt & 1;
        if (kt < NKT - 1) CP_WAIT1(); else CP_WAIT0();
        __syncthreads();

        const uint32_t kHi = sb + KB(cur);
        const uint32_t vHi = sb + KB(cur) + KB_VHI;

        // ---- sim = Q @ K^T ----
        float sc[8][4];
#pragma unroll
        for (int n = 0; n < 8; n++)
#pragma unroll
            for (int c = 0; c < 4; c++) sc[n][c] = 0.f;

#pragma unroll
        for (int c = 0; c < 4; c++) {
#pragma unroll
            for (int g = 0; g < 4; g++) {
                uint32_t bOff = (uint32_t)((g * 16 + ((lane >> 4) << 3) + (lane & 7)) * AS
                                           + ((lane >> 3) & 1) * 16 + c * 32);
                uint32_t th[4], tl[4];
                ldsm_x4(th, kHi + bOff);
                ldsm_x4(tl, kHi + KB_KLO + bOff);
                mma_bf16(sc[2 * g],     qh[c], th);
                mma_bf16(sc[2 * g],     qh[c], tl);
                mma_bf16(sc[2 * g],     ql[c], th);
                mma_bf16(sc[2 * g + 1], qh[c], th + 2);
                mma_bf16(sc[2 * g + 1], qh[c], tl + 2);
                mma_bf16(sc[2 * g + 1], ql[c], th + 2);
            }
        }

        // ---- Gaussian aug + mask ----
#pragma unroll
        for (int n = 0; n < 8; n++) {
            int kc0 = k0 + n * 8 + (lane & 3) * 2;
            float kxa = kxA[kc0],     kya = kyA[kc0],     kma = kmA[kc0];
            float kxb = kxA[kc0 + 1], kyb = kyA[kc0 + 1], kmb = kmA[kc0 + 1];
            float dxa1 = gx1 - kxa, dya1 = gy1 - kya;
            float dxb1 = gx1 - kxb, dyb1 = gy1 - kyb;
            float dxa2 = gx2 - kxa, dya2 = gy2 - kya;
            float dxb2 = gx2 - kxb, dyb2 = gy2 - kyb;
            sc[n][0] += al1 * __expf(-dxa1 * dxa1 * ix1 - dya1 * dya1 * iy1) + kma;
            sc[n][1] += al1 * __expf(-dxb1 * dxb1 * ix1 - dyb1 * dyb1 * iy1) + kmb;
            sc[n][2] += al2 * __expf(-dxa2 * dxa2 * ix2 - dya2 * dya2 * iy2) + kma;
            sc[n][3] += al2 * __expf(-dxb2 * dxb2 * ix2 - dyb2 * dyb2 * iy2) + kmb;
        }

        // ---- online softmax ----
        float mx1 = -1e30f, mx2 = -1e30f;
#pragma unroll
        for (int n = 0; n < 8; n++) {
            mx1 = fmaxf(mx1, fmaxf(sc[n][0], sc[n][1]));
            mx2 = fmaxf(mx2, fmaxf(sc[n][2], sc[n][3]));
        }
        mx1 = fmaxf(mx1, __shfl_xor_sync(0xffffffffu, mx1, 1));
        mx1 = fmaxf(mx1, __shfl_xor_sync(0xffffffffu, mx1, 2));
        mx2 = fmaxf(mx2, __shfl_xor_sync(0xffffffffu, mx2, 1));
        mx2 = fmaxf(mx2, __shfl_xor_sync(0xffffffffu, mx2, 2));

        float mnew1 = fmaxf(m1, mx1), mnew2 = fmaxf(m2, mx2);
        float scf1 = __expf(m1 - mnew1), scf2 = __expf(m2 - mnew2);
        m1 = mnew1; m2 = mnew2;

        float sum1 = 0.f, sum2 = 0.f;
#pragma unroll
        for (int n = 0; n < 8; n++) {
            float p0 = __expf(sc[n][0] - m1);
            float p1 = __expf(sc[n][1] - m1);
            float p2 = __expf(sc[n][2] - m2);
            float p3 = __expf(sc[n][3] - m2);
            sc[n][0] = p0; sc[n][1] = p1; sc[n][2] = p2; sc[n][3] = p3;
            sum1 += p0 + p1; sum2 += p2 + p3;
        }
        sum1 += __shfl_xor_sync(0xffffffffu, sum1, 1);
        sum1 += __shfl_xor_sync(0xffffffffu, sum1, 2);
        sum2 += __shfl_xor_sync(0xffffffffu, sum2, 1);
        sum2 += __shfl_xor_sync(0xffffffffu, sum2, 2);
        l1 = l1 * scf1 + sum1;
        l2 = l2 * scf2 + sum2;
#pragma unroll
        for (int n = 0; n < 8; n++) {
            oacc[n][0] *= scf1; oacc[n][1] *= scf1;
            oacc[n][2] *= scf2; oacc[n][3] *= scf2;
        }

        // ---- PV ----
#pragma unroll
        for (int c = 0; c < 4; c++) {
            uint32_t ahi[4], alo[4];
#pragma unroll
            for (int t = 0; t < 2; t++) {
                float p0 = sc[2 * c + t][0], p1 = sc[2 * c + t][1];
                float p2 = sc[2 * c + t][2], p3 = sc[2 * c + t][3];
                uint32_t h01 = pk_bf2(p0, p1);
                uint32_t h23 = pk_bf2(p2, p3);
                float r0 = p0 - __uint_as_float(h01 << 16);
                float r1b = p1 - __uint_as_float(h01 & 0xffff0000u);
                float r2 = p2 - __uint_as_float(h23 << 16);
                float r3 = p3 - __uint_as_float(h23 & 0xffff0000u);
                ahi[2 * t]     = h01;
                ahi[2 * t + 1] = h23;
                alo[2 * t]     = pk_bf2(r0, r1b);
                alo[2 * t + 1] = pk_bf2(r2, r3);
            }
            uint32_t af_hi[4] = {ahi[0], ahi[1], ahi[2], ahi[3]};
            uint32_t af_lo[4] = {alo[0], alo[1], alo[2], alo[3]};
#pragma unroll
            for (int g = 0; g < 4; g++) {
                uint32_t bOff = (uint32_t)((g * 16 + ((lane >> 4) << 3) + (lane & 7)) * AS
                                           + ((lane >> 3) & 1) * 16 + c * 32);
                uint32_t th[4], tl[4];
                ldsm_x4(th, vHi + bOff);
                ldsm_x4(tl, vHi + (KB_VLO - KB_VHI) + bOff);
                mma_bf16(oacc[2 * g],     af_hi, th);
                mma_bf16(oacc[2 * g],     af_hi, tl);
                mma_bf16(oacc[2 * g],     af_lo, th);
                mma_bf16(oacc[2 * g + 1], af_hi, th + 2);
                mma_bf16(oacc[2 * g + 1], af_hi, tl + 2);
                mma_bf16(oacc[2 * g + 1], af_lo, th + 2);
            }
        }

        __syncthreads();   // done reading buffer cur
        if (kt < NKT - 2) {
            const int k0n = (kt + 2) * KT;
            attn_cp_tile(sb, tid, krow0 + k0n, vbase, k0n, KB(cur));
            CP_COMMIT();
        }
    }

    // ---- final normalize + write ----
    float inv1 = 1.f / l1, inv2 = 1.f / l2;
    int qi1 = q0 + wid * 16 + r1;
    int qi2 = qi1 + 8;
#pragma unroll
    for (int n = 0; n < 8; n++) {
        int h = n * 8 + (lane & 3) * 2;
        if (qi1 < T_LEN) {
            float2 o = make_float2(oacc[n][0] * inv1, oacc[n][1] * inv1);
            *(float2*)&out[base + (size_t)qi1 * H_DIM + h] = o;
        }
        if (qi2 < T_LEN) {
            float2 o = make_float2(oacc[n][2] * inv2, oacc[n][3] * inv2);
            *(float2*)&out[base + (size_t)qi2 * H_DIM + h] = o;
        }
    }
}

// ---------------------------------------------------------------------------
extern "C" void kernel_launch(void* const* d_in, const int* in_sizes, int n_in,
                              void* d_out, int out_size)
{
    const float* x       = (const float*)d_in[0];
    const float* w_q     = (const float*)d_in[1];
    const float* w_k     = (const float*)d_in[2];
    const float* w_v     = (const float*)d_in[3];
    const float* q_gamma = (const float*)d_in[4];
    const float* q_beta  = (const float*)d_in[5];
    const float* k_gamma = (const float*)d_in[6];
    const float* k_beta  = (const float*)d_in[7];
    const float* w_sigma = (const float*)d_in[8];
    const float* b_sigma = (const float*)d_in[9];
    const float* w_alpha = (const float*)d_in[10];
    const float* b_alpha = (const float*)d_in[11];
    float* out = (float*)d_out;

    prep_w_kernel<<<(192 * E_DIM + 255) / 256, 256>>>(w_q, w_k, w_v);
    pad_kernel<<<(B_SZ * H_DIM * (TPAD - T_LEN) + 255) / 256, 256>>>();

    cudaFuncSetAttribute(qkv_mma_kernel, cudaFuncAttributeMaxDynamicSharedMemorySize, SM_TOTAL);
    qkv_mma_kernel<<<M_ROWS / 64, 256, SM_TOTAL>>>(x, q_gamma, q_beta, k_gamma, k_beta);

    cudaFuncSetAttribute(attn_mma_kernel, cudaFuncAttributeMaxDynamicSharedMemorySize, A_TOTAL);
    dim3 grid2((T_LEN + 127) / 128, B_SZ);
    attn_mma_kernel<<<grid2, 256, A_TOTAL>>>(w_sigma, b_sigma, w_alpha, b_alpha, out);
}

// round 14
// speedup vs baseline: 2.8369x; 1.0532x over previous
#include <cuda_runtime.h>
#include <cuda_bf16.h>
#include <math.h>
#include <stdint.h>

#define M_ROWS 36928   // B*T = 64*577
#define E_DIM  768
#define H_DIM  64
#define T_LEN  577
#define B_SZ   64
#define GW     24
#define TPAD   640     // padded T for transposed V

// scratch (static device arrays; no allocation)
__device__ float g_q[M_ROWS * H_DIM];
__device__ __nv_bfloat16 g_k_hi[(M_ROWS + 64) * H_DIM];
__device__ __nv_bfloat16 g_k_lo[(M_ROWS + 64) * H_DIM];
__device__ __nv_bfloat16 g_vT_hi[B_SZ * H_DIM * TPAD];
__device__ __nv_bfloat16 g_vT_lo[B_SZ * H_DIM * TPAD];
__device__ __nv_bfloat16 g_wcat_hi[192 * E_DIM];
__device__ __nv_bfloat16 g_wcat_lo[192 * E_DIM];

__device__ __forceinline__ uint32_t smem_u32(const void* p) {
    uint32_t a;
    asm("{ .reg .u64 t; cvta.to.shared.u64 t, %1; cvt.u32.u64 %0, t; }" : "=r"(a) : "l"(p));
    return a;
}
__device__ __forceinline__ void ldsm_x4(uint32_t* r, uint32_t addr) {
    asm volatile("ldmatrix.sync.aligned.m8n8.x4.shared.b16 {%0,%1,%2,%3}, [%4];"
                 : "=r"(r[0]), "=r"(r[1]), "=r"(r[2]), "=r"(r[3]) : "r"(addr));
}
__device__ __forceinline__ void mma_bf16(float* d, const uint32_t* a, const uint32_t* b) {
    asm volatile(
        "mma.sync.aligned.m16n8k16.row.col.f32.bf16.bf16.f32 "
        "{%0,%1,%2,%3}, {%4,%5,%6,%7}, {%8,%9}, {%0,%1,%2,%3};"
        : "+f"(d[0]), "+f"(d[1]), "+f"(d[2]), "+f"(d[3])
        : "r"(a[0]), "r"(a[1]), "r"(a[2]), "r"(a[3]), "r"(b[0]), "r"(b[1]));
}
__device__ __forceinline__ uint32_t packbf(__nv_bfloat16 a, __nv_bfloat16 b) {
    uint16_t ua = *(uint16_t*)&a, ub = *(uint16_t*)&b;
    return (uint32_t)ua | ((uint32_t)ub << 16);
}
__device__ __forceinline__ uint32_t pk_bf2(float lo, float hi) {
    uint32_t r; asm("cvt.rn.bf16x2.f32 %0, %1, %2;" : "=r"(r) : "f"(hi), "f"(lo)); return r;
}
__device__ __forceinline__ void cp16(uint32_t saddr, const void* gaddr) {
    asm volatile("cp.async.ca.shared.global [%0], [%1], 16;" :: "r"(saddr), "l"(gaddr) : "memory");
}
#define CP_COMMIT() asm volatile("cp.async.commit_group;" ::: "memory")
#define CP_WAIT1()  asm volatile("cp.async.wait_group 1;" ::: "memory")
#define CP_WAIT0()  asm volatile("cp.async.wait_group 0;" ::: "memory")

// ---------------------------------------------------------------------------
// Kernel 0a: weight prep
// ---------------------------------------------------------------------------
__global__ void prep_w_kernel(const float* __restrict__ w_q, const float* __restrict__ w_k,
                              const float* __restrict__ w_v)
{
    int idx = blockIdx.x * blockDim.x + threadIdx.x;
    if (idx >= 192 * E_DIM) return;
    int n = idx / E_DIM, k = idx % E_DIM;
    const float* w = (n < 64) ? w_q : (n < 128) ? w_k : w_v;
    float v = w[k * H_DIM + (n & 63)];
    __nv_bfloat16 hi = __float2bfloat16(v);
    __nv_bfloat16 lo = __float2bfloat16(v - __bfloat162float(hi));
    g_wcat_hi[idx] = hi;
    g_wcat_lo[idx] = lo;
}

// ---------------------------------------------------------------------------
// Kernel 0b: zero padding regions
// ---------------------------------------------------------------------------
__global__ void pad_kernel()
{
    int idx = blockIdx.x * blockDim.x + threadIdx.x;
    const __nv_bfloat16 z = __float2bfloat16(0.f);
    if (idx < 64 * H_DIM) {
        g_k_hi[(size_t)M_ROWS * H_DIM + idx] = z;
        g_k_lo[(size_t)M_ROWS * H_DIM + idx] = z;
    }
    const int NPAD = TPAD - T_LEN;
    const int NV = B_SZ * H_DIM * NPAD;
    if (idx < NV) {
        int b = idx / (H_DIM * NPAD);
        int rem = idx % (H_DIM * NPAD);
        int h = rem / NPAD;
        int j = rem % NPAD;
        size_t pos = ((size_t)(b * H_DIM + h)) * TPAD + T_LEN + j;
        g_vT_hi[pos] = z;
        g_vT_lo[pos] = z;
    }
}

// ---------------------------------------------------------------------------
// Kernel 1: split-bf16 mma.sync QKV GEMM + LayerNorm (R13, unchanged)
// ---------------------------------------------------------------------------
#define GK 64
#define NCHUNK (E_DIM / GK)
#define AS 144
#define A_LO_OFF 9216
#define ABUF(i) ((i) * 18432)
#define B_LO_OFF 27648
#define BBUF(i) (36864 + (i) * 55296)
#define SM_TOTAL (36864 + 2 * 55296)
#define STG_S 201

__device__ __forceinline__ void qkv_store_A(char* smc, int tid, const float4* av, uint32_t abuf)
{
#pragma unroll
    for (int it = 0; it < 4; it++) {
        int i = tid + it * 256;
        int r = i >> 4, col = (i & 15) * 4;
        float4 v = av[it];
        __nv_bfloat16 h0 = __float2bfloat16(v.x), h1 = __float2bfloat16(v.y);
        __nv_bfloat16 h2 = __float2bfloat16(v.z), h3 = __float2bfloat16(v.w);
        __nv_bfloat16 l0 = __float2bfloat16(v.x - __bfloat162float(h0));
        __nv_bfloat16 l1 = __float2bfloat16(v.y - __bfloat162float(h1));
        __nv_bfloat16 l2 = __float2bfloat16(v.z - __bfloat162float(h2));
        __nv_bfloat16 l3 = __float2bfloat16(v.w - __bfloat162float(h3));
        uint32_t off = abuf + (uint32_t)(r * AS + col * 2);
        *(uint2*)(smc + off)            = make_uint2(packbf(h0, h1), packbf(h2, h3));
        *(uint2*)(smc + off + A_LO_OFF) = make_uint2(packbf(l0, l1), packbf(l2, l3));
    }
}
__device__ __forceinline__ void qkv_cp_B(uint32_t sb, int tid, int k0, uint32_t bbuf)
{
#pragma unroll
    for (int it = 0; it < 6; it++) {
        int i = tid + it * 256;
        int r = i >> 3, seg = i & 7;
        uint32_t soff = sb + bbuf + (uint32_t)(r * AS + seg * 16);
        size_t goff = (size_t)r * E_DIM + k0 + seg * 8;
        cp16(soff,            g_wcat_hi + goff);
        cp16(soff + B_LO_OFF, g_wcat_lo + goff);
    }
}

__global__ __launch_bounds__(256) void qkv_mma_kernel(
    const float* __restrict__ x,
    const float* __restrict__ q_gamma, const float* __restrict__ q_beta,
    const float* __restrict__ k_gamma, const float* __restrict__ k_beta)
{
    extern __shared__ char smc[];
    const uint32_t sb = smem_u32(smc);
    const int tid  = threadIdx.x;
    const int wid  = tid >> 5;
    const int lane = tid & 31;
    const int wm   = wid >> 2;
    const int wn   = wid & 3;
    const int m0   = blockIdx.x * 64;

    const uint32_t aOff = (uint32_t)((wm * 32 + (lane & 15)) * AS + (lane >> 4) * 16);
    const uint32_t bOff = (uint32_t)((wn * 48 + ((lane >> 4) << 3) + (lane & 7)) * AS
                                     + ((lane >> 3) & 1) * 16);

    float acc[2][6][4];
#pragma unroll
    for (int i = 0; i < 2; i++)
#pragma unroll
        for (int j = 0; j < 6; j++)
#pragma unroll
            for (int c = 0; c < 4; c++) acc[i][j][c] = 0.f;

    float4 av[4];
    qkv_cp_B(sb, tid, 0, BBUF(0));
    CP_COMMIT();
#pragma unroll
    for (int it = 0; it < 4; it++) {
        int i = tid + it * 256;
        int r = i >> 4, col = (i & 15) * 4;
        av[it] = *(const float4*)&x[(size_t)(m0 + r) * E_DIM + 0 + col];
    }
    qkv_store_A(smc, tid, av, ABUF(0));
    qkv_cp_B(sb, tid, GK, BBUF(1));
    CP_COMMIT();
#pragma unroll
    for (int it = 0; it < 4; it++) {
        int i = tid + it * 256;
        int r = i >> 4, col = (i & 15) * 4;
        av[it] = *(const float4*)&x[(size_t)(m0 + r) * E_DIM + GK + col];
    }

    for (int ch = 0; ch < NCHUNK; ch++) {
        const int cur = ch & 1;
        if (ch < NCHUNK - 1) CP_WAIT1(); else CP_WAIT0();
        __syncthreads();

        const uint32_t aHi = sb + ABUF(cur) + aOff;
        const uint32_t bHi = sb + BBUF(cur) + bOff;
#pragma unroll
        for (int ks = 0; ks < 4; ks++) {
            const uint32_t kb = (uint32_t)(ks * 32);
            uint32_t ahi[2][4], alo[2][4];
#pragma unroll
            for (int im = 0; im < 2; im++) {
                ldsm_x4(ahi[im], aHi + im * 16 * AS + kb);
                ldsm_x4(alo[im], aHi + A_LO_OFF + im * 16 * AS + kb);
            }
            uint32_t bhi[6][2], blo[6][2];
#pragma unroll
            for (int j = 0; j < 3; j++) {
                uint32_t t[4];
                ldsm_x4(t, bHi + j * 16 * AS + kb);
                bhi[2 * j][0] = t[0]; bhi[2 * j][1] = t[1];
                bhi[2 * j + 1][0] = t[2]; bhi[2 * j + 1][1] = t[3];
                ldsm_x4(t, bHi + B_LO_OFF + j * 16 * AS + kb);
                blo[2 * j][0] = t[0]; blo[2 * j][1] = t[1];
                blo[2 * j + 1][0] = t[2]; blo[2 * j + 1][1] = t[3];
            }
#pragma unroll
            for (int im = 0; im < 2; im++)
#pragma unroll
                for (int jn = 0; jn < 6; jn++) {
                    mma_bf16(acc[im][jn], ahi[im], bhi[jn]);
                    mma_bf16(acc[im][jn], ahi[im], blo[jn]);
                    mma_bf16(acc[im][jn], alo[im], bhi[jn]);
                }
        }

        if (ch < NCHUNK - 1)
            qkv_store_A(smc, tid, av, ABUF((ch + 1) & 1));
        __syncthreads();

        if (ch < NCHUNK - 2) {
            const int k0n = (ch + 2) * GK;
            qkv_cp_B(sb, tid, k0n, BBUF(cur));
            CP_COMMIT();
#pragma unroll
            for (int it = 0; it < 4; it++) {
                int i = tid + it * 256;
                int r = i >> 4, col = (i & 15) * 4;
                av[it] = *(const float4*)&x[(size_t)(m0 + r) * E_DIM + k0n + col];
            }
        }
    }
    __syncthreads();

    float* stage = (float*)smc;
#pragma unroll
    for (int im = 0; im < 2; im++)
#pragma unroll
        for (int jn = 0; jn < 6; jn++) {
            int row = wm * 32 + im * 16 + (lane >> 2);
            int col = wn * 48 + jn * 8 + (lane & 3) * 2;
            stage[row * STG_S + col]           = acc[im][jn][0];
            stage[row * STG_S + col + 1]       = acc[im][jn][1];
            stage[(row + 8) * STG_S + col]     = acc[im][jn][2];
            stage[(row + 8) * STG_S + col + 1] = acc[im][jn][3];
        }
    __syncthreads();

    if (tid < 192) {
        int row = tid & 63;
        int seg = tid >> 6;
        int m = m0 + row;
        float f[64];
#pragma unroll
        for (int c = 0; c < 64; c++) f[c] = stage[row * STG_S + seg * 64 + c];
        if (seg < 2) {
            const float* gamma = (seg == 0) ? q_gamma : k_gamma;
            const float* beta  = (seg == 0) ? q_beta  : k_beta;
            float s = 0.f;
#pragma unroll
            for (int c = 0; c < 64; c++) s += f[c];
            float mu = s * (1.f / 64.f);
            float v2 = 0.f;
#pragma unroll
            for (int c = 0; c < 64; c++) { float d = f[c] - mu; v2 += d * d; }
            float rstd = rsqrtf(v2 * (1.f / 64.f) + 1e-5f);
#pragma unroll
            for (int c = 0; c < 64; c++) f[c] = (f[c] - mu) * rstd * gamma[c] + beta[c];
        }
        if (seg == 0) {
            size_t dst = (size_t)m * H_DIM;
#pragma unroll
            for (int c4 = 0; c4 < 16; c4++)
                *(float4*)&g_q[dst + c4 * 4] =
                    make_float4(f[c4 * 4], f[c4 * 4 + 1], f[c4 * 4 + 2], f[c4 * 4 + 3]);
        } else if (seg == 1) {
            uint32_t hp[32], lp[32];
#pragma unroll
            for (int c2 = 0; c2 < 32; c2++) {
                __nv_bfloat16 h0 = __float2bfloat16(f[2 * c2]);
                __nv_bfloat16 h1 = __float2bfloat16(f[2 * c2 + 1]);
                __nv_bfloat16 l0 = __float2bfloat16(f[2 * c2] - __bfloat162float(h0));
                __nv_bfloat16 l1 = __float2bfloat16(f[2 * c2 + 1] - __bfloat162float(h1));
                hp[c2] = packbf(h0, h1);
                lp[c2] = packbf(l0, l1);
            }
            uint4* dh = (uint4*)(g_k_hi + (size_t)m * H_DIM);
            uint4* dl = (uint4*)(g_k_lo + (size_t)m * H_DIM);
#pragma unroll
            for (int c = 0; c < 8; c++) {
                dh[c] = *(uint4*)&hp[c * 4];
                dl[c] = *(uint4*)&lp[c * 4];
            }
        } else {
            int bb = m / T_LEN;
            int t  = m - bb * T_LEN;
            __nv_bfloat16* dh = g_vT_hi + ((size_t)bb * H_DIM) * TPAD + t;
            __nv_bfloat16* dl = g_vT_lo + ((size_t)bb * H_DIM) * TPAD + t;
#pragma unroll
            for (int h = 0; h < 64; h++) {
                __nv_bfloat16 hi = __float2bfloat16(f[h]);
                __nv_bfloat16 lo = __float2bfloat16(f[h] - __bfloat162float(hi));
                dh[(size_t)h * TPAD] = hi;
                dl[(size_t)h * TPAD] = lo;
            }
        }
    }
}

// ---------------------------------------------------------------------------
// Kernel 2 (v9): mma.sync flash attention — 128 threads (4 warps), QT=64,
// 2 CTAs/SM for phase desynchronization. Per-warp code identical to v8.
// ---------------------------------------------------------------------------
#define KT 64
#define NKT 10
#define QT 64
#define AQ_HI 0
#define AQ_LO 9216
#define KB(i)  (18432 + (i) * 36864)
#define KB_KLO 9216
#define KB_VHI 18432
#define KB_VLO 27648
#define AP_OFF 92160
// params: al,ix,iy,gx,gy (5*64 fl) then kxA,kyA,kmA (3*640 fl)
#define A_TOTAL (AP_OFF + (5 * QT + 3 * TPAD) * 4)

__device__ __forceinline__ void attn_cp_tile(uint32_t sb, int tid, int krow0, int vbase, int k0,
                                             uint32_t buf)
{
    // K tile: 64 rows x 128B, hi+lo  (512 cp16 pairs / 128 threads = 4 iters)
#pragma unroll
    for (int it = 0; it < 4; it++) {
        int i = tid + it * 128;
        int r = i >> 3, seg = i & 7;
        uint32_t soff = sb + buf + (uint32_t)(r * AS + seg * 16);
        size_t g = ((size_t)(krow0 + r)) * H_DIM + seg * 8;
        cp16(soff,          g_k_hi + g);
        cp16(soff + KB_KLO, g_k_lo + g);
    }
    // V tile: 64 h-rows x 128B (k slice), hi+lo
#pragma unroll
    for (int it = 0; it < 4; it++) {
        int i = tid + it * 128;
        int h = i >> 3, seg = i & 7;
        uint32_t soff = sb + buf + KB_VHI + (uint32_t)(h * AS + seg * 16);
        size_t g = ((size_t)(vbase + h)) * TPAD + k0 + seg * 8;
        cp16(soff,                     g_vT_hi + g);
        cp16(soff + (KB_VLO - KB_VHI), g_vT_lo + g);
    }
}

__global__ __launch_bounds__(128) void attn_mma_kernel(
    const float* __restrict__ w_sigma, const float* __restrict__ b_sigma,
    const float* __restrict__ w_alpha, const float* __restrict__ b_alpha,
    float* __restrict__ out)
{
    extern __shared__ char smc[];
    const uint32_t sb = smem_u32(smc);
    float* al_s = (float*)(smc + AP_OFF);
    float* ix_s = al_s + QT;
    float* iy_s = ix_s + QT;
    float* gx_s = iy_s + QT;
    float* gy_s = gx_s + QT;
    float* kxA  = gy_s + QT;       // [TPAD]
    float* kyA  = kxA + TPAD;
    float* kmA  = kyA + TPAD;

    const int tid  = threadIdx.x;
    const int lane = tid & 31;
    const int wid  = tid >> 5;     // 0..3
    const int b    = blockIdx.y;
    const int q0   = blockIdx.x * QT;
    const size_t base = (size_t)b * T_LEN * H_DIM;
    const int krow0 = b * T_LEN;
    const int vbase = b * H_DIM;

    // start streaming tiles 0 and 1 immediately
    attn_cp_tile(sb, tid, krow0 + 0,  vbase, 0,  KB(0));
    CP_COMMIT();
    attn_cp_tile(sb, tid, krow0 + KT, vbase, KT, KB(1));
    CP_COMMIT();

    // ---- load Q (fold 0.125), split bf16 hi/lo (64 rows x 16 f4 = 1024) ----
#pragma unroll
    for (int it = 0; it < 8; it++) {
        int i = tid + it * 128;
        int r = i >> 4, c4 = i & 15;
        int qi = q0 + r;
        float4 v = make_float4(0.f, 0.f, 0.f, 0.f);
        if (qi < T_LEN) v = *(const float4*)&g_q[base + (size_t)qi * H_DIM + c4 * 4];
        v.x *= 0.125f; v.y *= 0.125f; v.z *= 0.125f; v.w *= 0.125f;
        __nv_bfloat16 h0 = __float2bfloat16(v.x), h1 = __float2bfloat16(v.y);
        __nv_bfloat16 h2 = __float2bfloat16(v.z), h3 = __float2bfloat16(v.w);
        __nv_bfloat16 l0 = __float2bfloat16(v.x - __bfloat162float(h0));
        __nv_bfloat16 l1 = __float2bfloat16(v.y - __bfloat162float(h1));
        __nv_bfloat16 l2 = __float2bfloat16(v.z - __bfloat162float(h2));
        __nv_bfloat16 l3 = __float2bfloat16(v.w - __bfloat162float(h3));
        uint32_t off = (uint32_t)(r * AS + c4 * 8);
        *(uint2*)(smc + AQ_HI + off) = make_uint2(packbf(h0, h1), packbf(h2, h3));
        *(uint2*)(smc + AQ_LO + off) = make_uint2(packbf(l0, l1), packbf(l2, l3));
    }

    // ---- per-q-row aug params ----
    if (tid < QT) {
        int r = tid;
        int qi = q0 + r;
        if (qi >= 1 && qi < T_LEN) {
            const float* qrow = &g_q[base + (size_t)qi * H_DIM];
            float a = 0.f, s0 = 0.f, s1 = 0.f;
#pragma unroll 8
            for (int c = 0; c < 64; c++) {
                float qv = qrow[c];
                a  += qv * w_alpha[c];
                s0 += qv * w_sigma[c * 2 + 0];
                s1 += qv * w_sigma[c * 2 + 1];
            }
            a += b_alpha[0]; s0 += b_sigma[0]; s1 += b_sigma[1];
            float alpha = fmaxf(a, 0.f) + log1pf(expf(-fabsf(a)));
            float sx = 1.f / (1.f + expf(-s0));
            float sy = 1.f / (1.f + expf(-s1));
            al_s[r] = alpha * 0.125f;
            ix_s[r] = 0.5f / (sx * sx);
            iy_s[r] = 0.5f / (sy * sy);
            int gq = qi - 1;
            gx_s[r] = (float)(gq % GW);
            gy_s[r] = (float)(gq / GW);
        } else {
            al_s[r] = 0.f; ix_s[r] = 0.f; iy_s[r] = 0.f;
            gx_s[r] = 0.f; gy_s[r] = 0.f;
        }
    }
    // ---- k-column grid tables (once per block) ----
#pragma unroll
    for (int it = 0; it < 5; it++) {
        int ki = tid + it * 128;
        if (ki < TPAD) {
            bool kvalid = ki < T_LEN;
            bool kaug = (ki >= 1) && kvalid;
            int g = kaug ? ki - 1 : 0;
            kxA[ki] = kaug ? (float)(g % GW) : -1e9f;
            kyA[ki] = kaug ? (float)(g / GW) : 0.f;
            kmA[ki] = kvalid ? 0.f : -1e30f;
        }
    }
    __syncthreads();

    // ---- Q fragments resident in registers (warp w: rows 16w..16w+15) ----
    uint32_t qh[4][4], ql[4][4];
    {
        uint32_t aOff = (uint32_t)((wid * 16 + (lane & 15)) * AS + (lane >> 4) * 16);
#pragma unroll
        for (int c = 0; c < 4; c++) {
            ldsm_x4(qh[c], sb + AQ_HI + aOff + c * 32);
            ldsm_x4(ql[c], sb + AQ_LO + aOff + c * 32);
        }
    }

    const int r1  = lane >> 2;
    const int lr1 = wid * 16 + r1;
    const float al1 = al_s[lr1],     ix1 = ix_s[lr1],     iy1 = iy_s[lr1];
    const float gx1 = gx_s[lr1],     gy1 = gy_s[lr1];
    const float al2 = al_s[lr1 + 8], ix2 = ix_s[lr1 + 8], iy2 = iy_s[lr1 + 8];
    const float gx2 = gx_s[lr1 + 8], gy2 = gy_s[lr1 + 8];

    float m1 = -1e30f, m2 = -1e30f, l1 = 0.f, l2 = 0.f;
    float oacc[8][4];
#pragma unroll
    for (int n = 0; n < 8; n++)
#pragma unroll
        for (int c = 0; c < 4; c++) oacc[n][c] = 0.f;

    for (int kt = 0; kt < NKT; kt++) {
        const int k0 = kt * KT;
        const int cur = kt & 1;
        if (kt < NKT - 1) CP_WAIT1(); else CP_WAIT0();
        __syncthreads();

        const uint32_t kHi = sb + KB(cur);
        const uint32_t vHi = sb + KB(cur) + KB_VHI;

        // ---- sim = Q @ K^T ----
        float sc[8][4];
#pragma unroll
        for (int n = 0; n < 8; n++)
#pragma unroll
            for (int c = 0; c < 4; c++) sc[n][c] = 0.f;

#pragma unroll
        for (int c = 0; c < 4; c++) {
#pragma unroll
            for (int g = 0; g < 4; g++) {
                uint32_t bOff = (uint32_t)((g * 16 + ((lane >> 4) << 3) + (lane & 7)) * AS
                                           + ((lane >> 3) & 1) * 16 + c * 32);
                uint32_t th[4], tl[4];
                ldsm_x4(th, kHi + bOff);
                ldsm_x4(tl, kHi + KB_KLO + bOff);
                mma_bf16(sc[2 * g],     qh[c], th);
                mma_bf16(sc[2 * g],     qh[c], tl);
                mma_bf16(sc[2 * g],     ql[c], th);
                mma_bf16(sc[2 * g + 1], qh[c], th + 2);
                mma_bf16(sc[2 * g + 1], qh[c], tl + 2);
                mma_bf16(sc[2 * g + 1], ql[c], th + 2);
            }
        }

        // ---- Gaussian aug + mask ----
#pragma unroll
        for (int n = 0; n < 8; n++) {
            int kc0 = k0 + n * 8 + (lane & 3) * 2;
            float kxa = kxA[kc0],     kya = kyA[kc0],     kma = kmA[kc0];
            float kxb = kxA[kc0 + 1], kyb = kyA[kc0 + 1], kmb = kmA[kc0 + 1];
            float dxa1 = gx1 - kxa, dya1 = gy1 - kya;
            float dxb1 = gx1 - kxb, dyb1 = gy1 - kyb;
            float dxa2 = gx2 - kxa, dya2 = gy2 - kya;
            float dxb2 = gx2 - kxb, dyb2 = gy2 - kyb;
            sc[n][0] += al1 * __expf(-dxa1 * dxa1 * ix1 - dya1 * dya1 * iy1) + kma;
            sc[n][1] += al1 * __expf(-dxb1 * dxb1 * ix1 - dyb1 * dyb1 * iy1) + kmb;
            sc[n][2] += al2 * __expf(-dxa2 * dxa2 * ix2 - dya2 * dya2 * iy2) + kma;
            sc[n][3] += al2 * __expf(-dxb2 * dxb2 * ix2 - dyb2 * dyb2 * iy2) + kmb;
        }

        // ---- online softmax ----
        float mx1 = -1e30f, mx2 = -1e30f;
#pragma unroll
        for (int n = 0; n < 8; n++) {
            mx1 = fmaxf(mx1, fmaxf(sc[n][0], sc[n][1]));
            mx2 = fmaxf(mx2, fmaxf(sc[n][2], sc[n][3]));
        }
        mx1 = fmaxf(mx1, __shfl_xor_sync(0xffffffffu, mx1, 1));
        mx1 = fmaxf(mx1, __shfl_xor_sync(0xffffffffu, mx1, 2));
        mx2 = fmaxf(mx2, __shfl_xor_sync(0xffffffffu, mx2, 1));
        mx2 = fmaxf(mx2, __shfl_xor_sync(0xffffffffu, mx2, 2));

        float mnew1 = fmaxf(m1, mx1), mnew2 = fmaxf(m2, mx2);
        float scf1 = __expf(m1 - mnew1), scf2 = __expf(m2 - mnew2);
        m1 = mnew1; m2 = mnew2;

        float sum1 = 0.f, sum2 = 0.f;
#pragma unroll
        for (int n = 0; n < 8; n++) {
            float p0 = __expf(sc[n][0] - m1);
            float p1 = __expf(sc[n][1] - m1);
            float p2 = __expf(sc[n][2] - m2);
            float p3 = __expf(sc[n][3] - m2);
            sc[n][0] = p0; sc[n][1] = p1; sc[n][2] = p2; sc[n][3] = p3;
            sum1 += p0 + p1; sum2 += p2 + p3;
        }
        sum1 += __shfl_xor_sync(0xffffffffu, sum1, 1);
        sum1 += __shfl_xor_sync(0xffffffffu, sum1, 2);
        sum2 += __shfl_xor_sync(0xffffffffu, sum2, 1);
        sum2 += __shfl_xor_sync(0xffffffffu, sum2, 2);
        l1 = l1 * scf1 + sum1;
        l2 = l2 * scf2 + sum2;
#pragma unroll
        for (int n = 0; n < 8; n++) {
            oacc[n][0] *= scf1; oacc[n][1] *= scf1;
            oacc[n][2] *= scf2; oacc[n][3] *= scf2;
        }

        // ---- PV ----
#pragma unroll
        for (int c = 0; c < 4; c++) {
            uint32_t ahi[4], alo[4];
#pragma unroll
            for (int t = 0; t < 2; t++) {
                float p0 = sc[2 * c + t][0], p1 = sc[2 * c + t][1];
                float p2 = sc[2 * c + t][2], p3 = sc[2 * c + t][3];
                uint32_t h01 = pk_bf2(p0, p1);
                uint32_t h23 = pk_bf2(p2, p3);
                float r0 = p0 - __uint_as_float(h01 << 16);
                float r1b = p1 - __uint_as_float(h01 & 0xffff0000u);
                float r2 = p2 - __uint_as_float(h23 << 16);
                float r3 = p3 - __uint_as_float(h23 & 0xffff0000u);
                ahi[2 * t]     = h01;
                ahi[2 * t + 1] = h23;
                alo[2 * t]     = pk_bf2(r0, r1b);
                alo[2 * t + 1] = pk_bf2(r2, r3);
            }
            uint32_t af_hi[4] = {ahi[0], ahi[1], ahi[2], ahi[3]};
            uint32_t af_lo[4] = {alo[0], alo[1], alo[2], alo[3]};
#pragma unroll
            for (int g = 0; g < 4; g++) {
                uint32_t bOff = (uint32_t)((g * 16 + ((lane >> 4) << 3) + (lane & 7)) * AS
                                           + ((lane >> 3) & 1) * 16 + c * 32);
                uint32_t th[4], tl[4];
                ldsm_x4(th, vHi + bOff);
                ldsm_x4(tl, vHi + (KB_VLO - KB_VHI) + bOff);
                mma_bf16(oacc[2 * g],     af_hi, th);
                mma_bf16(oacc[2 * g],     af_hi, tl);
                mma_bf16(oacc[2 * g],     af_lo, th);
                mma_bf16(oacc[2 * g + 1], af_hi, th + 2);
                mma_bf16(oacc[2 * g + 1], af_hi, tl + 2);
                mma_bf16(oacc[2 * g + 1], af_lo, th + 2);
            }
        }

        __syncthreads();   // done reading buffer cur
        if (kt < NKT - 2) {
            const int k0n = (kt + 2) * KT;
            attn_cp_tile(sb, tid, krow0 + k0n, vbase, k0n, KB(cur));
            CP_COMMIT();
        }
    }

    // ---- final normalize + write ----
    float inv1 = 1.f / l1, inv2 = 1.f / l2;
    int qi1 = q0 + wid * 16 + r1;
    int qi2 = qi1 + 8;
#pragma unroll
    for (int n = 0; n < 8; n++) {
        int h = n * 8 + (lane & 3) * 2;
        if (qi1 < T_LEN) {
            float2 o = make_float2(oacc[n][0] * inv1, oacc[n][1] * inv1);
            *(float2*)&out[base + (size_t)qi1 * H_DIM + h] = o;
        }
        if (qi2 < T_LEN) {
            float2 o = make_float2(oacc[n][2] * inv2, oacc[n][3] * inv2);
            *(float2*)&out[base + (size_t)qi2 * H_DIM + h] = o;
        }
    }
}

// ---------------------------------------------------------------------------
extern "C" void kernel_launch(void* const* d_in, const int* in_sizes, int n_in,
                              void* d_out, int out_size)
{
    const float* x       = (const float*)d_in[0];
    const float* w_q     = (const float*)d_in[1];
    const float* w_k     = (const float*)d_in[2];
    const float* w_v     = (const float*)d_in[3];
    const float* q_gamma = (const float*)d_in[4];
    const float* q_beta  = (const float*)d_in[5];
    const float* k_gamma = (const float*)d_in[6];
    const float* k_beta  = (const float*)d_in[7];
    const float* w_sigma = (const float*)d_in[8];
    const float* b_sigma = (const float*)d_in[9];
    const float* w_alpha = (const float*)d_in[10];
    const float* b_alpha = (const float*)d_in[11];
    float* out = (float*)d_out;

    prep_w_kernel<<<(192 * E_DIM + 255) / 256, 256>>>(w_q, w_k, w_v);
    pad_kernel<<<(B_SZ * H_DIM * (TPAD - T_LEN) + 255) / 256, 256>>>();

    cudaFuncSetAttribute(qkv_mma_kernel, cudaFuncAttributeMaxDynamicSharedMemorySize, SM_TOTAL);
    qkv_mma_kernel<<<M_ROWS / 64, 256, SM_TOTAL>>>(x, q_gamma, q_beta, k_gamma, k_beta);

    cudaFuncSetAttribute(attn_mma_kernel, cudaFuncAttributeMaxDynamicSharedMemorySize, A_TOTAL);
    dim3 grid2((T_LEN + QT - 1) / QT, B_SZ);
    attn_mma_kernel<<<grid2, 128, A_TOTAL>>>(w_sigma, b_sigma, w_alpha, b_alpha, out);
}